// round 10
// baseline (speedup 1.0000x reference)
#include <cuda_runtime.h>
#include <cuda_bf16.h>
#include <math.h>
#include <stdint.h>

#define T_ 8
#define B_ 128
#define N_ 1024

// ---------------- static scratch ----------------
__device__ float g_y1[N_*64*32*32];          // conv1 out (268 MB)
__device__ __nv_bfloat16 g_s1b[N_*64*16*16]; // pooled spikes L1 (bf16, exact)
__device__ float g_y2[N_*128*16*16];         // conv2 out (134 MB)
__device__ float g_s2[N_*128*8*8];           // pooled spikes L2
__device__ float g_s3[N_*256];               // LIF spikes L3
__device__ float g_z1p[8*N_*256];            // fc1 K-split partials

__device__ __nv_bfloat16 g_a2[(size_t)2048*9*8192];   // conv2 im2col tiles, swizzled
__device__ __nv_bfloat16 g_b2[9*3*8192];              // conv2 weight tiles [kc][split]
__device__ __nv_bfloat16 g_afc[(size_t)8*128*8192];   // fc1 A tiles
__device__ __nv_bfloat16 g_bfc[(size_t)2*128*3*8192]; // fc1 B tiles

__device__ float g_p1parts[64*1024], g_p1partq[64*1024];   // conv1 fused stats partials
__device__ float g_p2parts[128*2048], g_p2partq[128*2048]; // conv2 fused stats partials
__device__ float g_scale1[64], g_shift1[64];
__device__ float g_scale2[128], g_shift2[128];

#define LIF_STEP(v, x, s)                         \
    {                                             \
        v = v + (x - v) * 0.5f;                   \
        s = (v >= 1.0f) ? 1.0f : 0.0f;            \
        v = (v >= 1.0f) ? 0.0f : v;               \
    }

__device__ __forceinline__ unsigned smem_u32(const void* p) {
    return (unsigned)__cvta_generic_to_shared(p);
}
__device__ __forceinline__ unsigned pack_bf2(__nv_bfloat16 a, __nv_bfloat16 b) {
    return (unsigned)__bfloat16_as_ushort(a) | ((unsigned)__bfloat16_as_ushort(b) << 16);
}

#define CP16(dst, src) \
    asm volatile("cp.async.cg.shared.global [%0], [%1], 16;" :: "r"(dst), "l"(src))
#define CP_COMMIT() asm volatile("cp.async.commit_group;" ::: "memory")
#define CP_WAIT1()  asm volatile("cp.async.wait_group 1;" ::: "memory")
#define CP_WAIT0()  asm volatile("cp.async.wait_group 0;" ::: "memory")

__device__ __forceinline__ void ldsm4(unsigned& r0, unsigned& r1, unsigned& r2, unsigned& r3,
                                      unsigned a) {
    asm volatile("ldmatrix.sync.aligned.m8n8.x4.shared.b16 {%0,%1,%2,%3}, [%4];"
                 : "=r"(r0), "=r"(r1), "=r"(r2), "=r"(r3) : "r"(a));
}
__device__ __forceinline__ void mma_bf16(float* c, const unsigned* a, const unsigned* b) {
    asm volatile("mma.sync.aligned.m16n8k16.row.col.f32.bf16.bf16.f32 "
                 "{%0,%1,%2,%3}, {%4,%5,%6,%7}, {%8,%9}, {%0,%1,%2,%3};"
                 : "+f"(c[0]), "+f"(c[1]), "+f"(c[2]), "+f"(c[3])
                 : "r"(a[0]), "r"(a[1]), "r"(a[2]), "r"(a[3]), "r"(b[0]), "r"(b[1]));
}

// ---------------- conv1: 3->64, 32x32, pad 1, fused BN1 stats partials ----------------
__global__ void __launch_bounds__(256) conv1_kernel(const float* __restrict__ x,
                                                    const float* __restrict__ w)
{
    __shared__ float s_in[3*34*34];
    __shared__ float s_w[64*27];
    __shared__ float c1s[8][8], c1q[8][8];
    const int n = blockIdx.x, tid = threadIdx.x;
    const int lane = tid & 31, wid = tid >> 5;

    for (int i = tid; i < 3*34*34; i += 256) s_in[i] = 0.0f;
    __syncthreads();
    for (int i = tid; i < 3*1024; i += 256) {
        int ci = i >> 10, p = i & 1023, h = p >> 5, wc = p & 31;
        s_in[ci*1156 + (h+1)*34 + (wc+1)] = x[n*3072 + i];
    }
    for (int i = tid; i < 1728; i += 256) s_w[i] = w[i];
    __syncthreads();

    int hh[4], ww[4];
#pragma unroll
    for (int j = 0; j < 4; j++) { int p = tid + j*256; hh[j] = p >> 5; ww[j] = p & 31; }

#pragma unroll 1
    for (int cb = 0; cb < 64; cb += 8) {
        float acc[8][4];
#pragma unroll
        for (int u = 0; u < 8; u++)
#pragma unroll
            for (int j = 0; j < 4; j++) acc[u][j] = 0.0f;

#pragma unroll
        for (int ci = 0; ci < 3; ci++)
#pragma unroll
        for (int kh = 0; kh < 3; kh++)
#pragma unroll
        for (int kw = 0; kw < 3; kw++) {
            const int k = ci*9 + kh*3 + kw;
            float wr[8];
#pragma unroll
            for (int u = 0; u < 8; u++) wr[u] = s_w[(cb+u)*27 + k];
#pragma unroll
            for (int j = 0; j < 4; j++) {
                float xv = s_in[ci*1156 + (hh[j]+kh)*34 + (ww[j]+kw)];
#pragma unroll
                for (int u = 0; u < 8; u++) acc[u][j] += wr[u] * xv;
            }
        }
#pragma unroll
        for (int u = 0; u < 8; u++)
#pragma unroll
            for (int j = 0; j < 4; j++)
                g_y1[(n*64 + cb + u)*1024 + tid + j*256] = acc[u][j];

#pragma unroll
        for (int u = 0; u < 8; u++) {
            float fs = acc[u][0] + acc[u][1] + acc[u][2] + acc[u][3];
            float fq = acc[u][0]*acc[u][0] + acc[u][1]*acc[u][1]
                     + acc[u][2]*acc[u][2] + acc[u][3]*acc[u][3];
#pragma unroll
            for (int off = 16; off > 0; off >>= 1) {
                fs += __shfl_xor_sync(0xffffffffu, fs, off);
                fq += __shfl_xor_sync(0xffffffffu, fq, off);
            }
            if (lane == 0) { c1s[wid][u] = fs; c1q[wid][u] = fq; }
        }
        __syncthreads();
        if (tid < 8) {
            float s = 0.0f, q = 0.0f;
#pragma unroll
            for (int wv = 0; wv < 8; wv++) { s += c1s[wv][tid]; q += c1q[wv][tid]; }
            g_p1parts[(cb + tid)*1024 + n] = s;
            g_p1partq[(cb + tid)*1024 + n] = q;
        }
        __syncthreads();
    }
}

__global__ void finalize1_kernel(const float* __restrict__ g, const float* __restrict__ b)
{
    int c = threadIdx.x;  // 64
    double s = 0.0, q = 0.0;
    for (int i = 0; i < 1024; i++) { s += (double)g_p1parts[c*1024 + i]; q += (double)g_p1partq[c*1024 + i]; }
    const double cnt = 1048576.0;
    double m = s / cnt, var = q / cnt - m*m;
    double sc = (double)g[c] / sqrt(var + 1e-5);
    g_scale1[c] = (float)sc;
    g_shift1[c] = (float)((double)b[c] - m*sc);
}

__global__ void finalize2_kernel(const float* __restrict__ g, const float* __restrict__ b)
{
    int c = threadIdx.x;  // 128
    double s = 0.0, q = 0.0;
    for (int i = 0; i < 2048; i++) { s += (double)g_p2parts[c*2048 + i]; q += (double)g_p2partq[c*2048 + i]; }
    const double cnt = 262144.0;
    double m = s / cnt, var = q / cnt - m*m;
    double sc = (double)g[c] / sqrt(var + 1e-5);
    g_scale2[c] = (float)sc;
    g_shift2[c] = (float)((double)b[c] - m*sc);
}

// ---------------- BN + LIF + pool, layer 1 (bf16 spike output) ----------------
__global__ void __launch_bounds__(256) lifpool1_kernel()
{
    const int bc = blockIdx.x;
    const int c = bc & 63, b = bc >> 6;
    const int tid = threadIdx.x;
    const int hg = tid >> 4, wg = tid & 15;
    const float sc = g_scale1[c], sh = g_shift1[c];
    float v0 = 0, v1 = 0, v2 = 0, v3 = 0;
#pragma unroll
    for (int t = 0; t < T_; t++) {
        const int n = t*B_ + b;
        const int base = (n*64 + c)*1024 + (hg*2)*32 + wg*2;
        float2 r0 = *reinterpret_cast<const float2*>(g_y1 + base);
        float2 r1 = *reinterpret_cast<const float2*>(g_y1 + base + 32);
        float x00 = r0.x*sc + sh, x01 = r0.y*sc + sh;
        float x10 = r1.x*sc + sh, x11 = r1.y*sc + sh;
        float s00, s01, s10, s11;
        LIF_STEP(v0, x00, s00); LIF_STEP(v1, x01, s01);
        LIF_STEP(v2, x10, s10); LIF_STEP(v3, x11, s11);
        g_s1b[(n*64 + c)*256 + hg*16 + wg] =
            __float2bfloat16((s00 + s01 + s10 + s11)*0.25f);
    }
}

// ---------------- conv2 weight 3-split into swizzled bf16 tiles ----------------
__global__ void __launch_bounds__(256) prep_conv2_w_kernel(const float* __restrict__ w)
{
    int gid = blockIdx.x*256 + threadIdx.x;     // 9*128*4 = 4608
    if (gid >= 4608) return;
    int c32 = gid & 3, co = (gid >> 2) & 127, kc = gid >> 9;
    unsigned hi[8], mid[8], lo[8];
    __nv_bfloat16 h2[2], m2[2], l2[2];
#pragma unroll
    for (int e = 0; e < 16; e++) {
        int k = kc*64 + c32*16 + e;
        float wv = w[co*576 + k];
        __nv_bfloat16 h = __float2bfloat16(wv);
        float r1 = wv - __bfloat162float(h);
        __nv_bfloat16 m = __float2bfloat16(r1);
        float r2 = r1 - __bfloat162float(m);
        __nv_bfloat16 l = __float2bfloat16(r2);
        h2[e & 1] = h; m2[e & 1] = m; l2[e & 1] = l;
        if (e & 1) {
            hi[e >> 1] = pack_bf2(h2[0], h2[1]);
            mid[e >> 1] = pack_bf2(m2[0], m2[1]);
            lo[e >> 1] = pack_bf2(l2[0], l2[1]);
        }
    }
    int r = co;
    int ua = r*8 + ((2*c32) ^ (r & 7));
    int ub = r*8 + ((2*c32 + 1) ^ (r & 7));
    for (int s = 0; s < 3; s++) {
        unsigned* src = (s == 0) ? hi : (s == 1) ? mid : lo;
        __nv_bfloat16* base = g_b2 + ((size_t)kc*3 + s)*8192;
        *(uint4*)(base + ua*8) = make_uint4(src[0], src[1], src[2], src[3]);
        *(uint4*)(base + ub*8) = make_uint4(src[4], src[5], src[6], src[7]);
    }
}

// ---------------- im2col for conv2 (reads bf16 spikes) ----------------
__global__ void __launch_bounds__(256) im2col2_kernel()
{
    int gid = blockIdx.x*256 + threadIdx.x;     // 9*4*262144
    int m = gid & 262143;
    int rest = gid >> 18;
    int c32 = rest & 3, kc = rest >> 2;
    int n = m >> 8, p = m & 255, h = p >> 4, w = p & 15;
    int mt = m >> 7, r = m & 127;
    unsigned pk[8];
    __nv_bfloat16 v2[2];
#pragma unroll
    for (int e = 0; e < 16; e++) {
        int k = kc*64 + c32*16 + e;
        int ci = k / 9, t9 = k - ci*9, kh = t9 / 3, kw = t9 - kh*3;
        int ih = h + kh - 1, iw = w + kw - 1;
        __nv_bfloat16 v = __float2bfloat16(0.0f);
        if ((unsigned)ih < 16u && (unsigned)iw < 16u)
            v = g_s1b[((n*64 + ci) << 8) + (ih << 4) + iw];
        v2[e & 1] = v;
        if (e & 1) pk[e >> 1] = pack_bf2(v2[0], v2[1]);
    }
    __nv_bfloat16* base = g_a2 + ((size_t)mt*9 + kc)*8192;
    int ua = r*8 + ((2*c32) ^ (r & 7));
    int ub = r*8 + ((2*c32 + 1) ^ (r & 7));
    *(uint4*)(base + ua*8) = make_uint4(pk[0], pk[1], pk[2], pk[3]);
    *(uint4*)(base + ub*8) = make_uint4(pk[4], pk[5], pk[6], pk[7]);
}

// ---------------- conv2 GEMM (R4 structure) + fused BN2 stats epilogue ----------------
__global__ void __launch_bounds__(256) conv2_gemm_kernel()
{
    extern __shared__ char dsm[];
    const unsigned sbase = smem_u32(dsm);
    const int tid = threadIdx.x, lane = tid & 31, wid = tid >> 5;
    const int mt = blockIdx.x;
    const int m0 = (wid & 3) * 32, n0 = (wid >> 2) * 64;

    float acc[2][8][4];
#pragma unroll
    for (int f = 0; f < 2; f++)
#pragma unroll
        for (int nf = 0; nf < 8; nf++)
#pragma unroll
            for (int q = 0; q < 4; q++) acc[f][nf][q] = 0.0f;

    {
        unsigned dst = sbase;
        const char* ag = (const char*)(g_a2 + ((size_t)mt*9 + 0)*8192);
#pragma unroll
        for (int i = 0; i < 4; i++)
            CP16(dst + (unsigned)(tid + i*256)*16, ag + (size_t)(tid + i*256)*16);
        const char* bg = (const char*)(g_b2);
#pragma unroll
        for (int i = 0; i < 12; i++)
            CP16(dst + 16384u + (unsigned)(tid + i*256)*16, bg + (size_t)(tid + i*256)*16);
        CP_COMMIT();
    }

#pragma unroll 1
    for (int kc = 0; kc < 9; kc++) {
        const int cur = kc & 1;
        if (kc < 8) {
            unsigned dst = sbase + (unsigned)(cur ^ 1)*65536u;
            const char* ag = (const char*)(g_a2 + ((size_t)mt*9 + kc + 1)*8192);
#pragma unroll
            for (int i = 0; i < 4; i++)
                CP16(dst + (unsigned)(tid + i*256)*16, ag + (size_t)(tid + i*256)*16);
            const char* bg = (const char*)(g_b2 + (size_t)(kc + 1)*3*8192);
#pragma unroll
            for (int i = 0; i < 12; i++)
                CP16(dst + 16384u + (unsigned)(tid + i*256)*16, bg + (size_t)(tid + i*256)*16);
            CP_COMMIT();
            CP_WAIT1();
        } else {
            CP_WAIT0();
        }
        __syncthreads();

        const unsigned sA = sbase + (unsigned)cur*65536u;
        const unsigned sB = sA + 16384u;

        unsigned afr[4][2][4];
#pragma unroll
        for (int ks = 0; ks < 4; ks++)
#pragma unroll
            for (int f = 0; f < 2; f++) {
                int row = m0 + f*16 + (lane & 15);
                int c16 = ks*2 + (lane >> 4);
                unsigned ad = sA + (unsigned)((row*8 + (c16 ^ (row & 7)))*16);
                ldsm4(afr[ks][f][0], afr[ks][f][1], afr[ks][f][2], afr[ks][f][3], ad);
            }

#pragma unroll 1
        for (int s = 0; s < 3; s++) {
            const unsigned bb = sB + (unsigned)s*16384u;
#pragma unroll
            for (int ks = 0; ks < 4; ks++) {
                unsigned bfr[8][2];
#pragma unroll
                for (int nb = 0; nb < 4; nb++) {
                    int row = n0 + nb*16 + (lane & 7) + ((lane >> 4) << 3);
                    int c16 = ks*2 + ((lane >> 3) & 1);
                    unsigned ad = bb + (unsigned)((row*8 + (c16 ^ (row & 7)))*16);
                    unsigned r0, r1, r2, r3;
                    ldsm4(r0, r1, r2, r3, ad);
                    bfr[2*nb][0] = r0; bfr[2*nb][1] = r1;
                    bfr[2*nb+1][0] = r2; bfr[2*nb+1][1] = r3;
                }
#pragma unroll
                for (int f = 0; f < 2; f++)
#pragma unroll
                    for (int nf = 0; nf < 8; nf++)
                        mma_bf16(acc[f][nf], afr[ks][f], bfr[nf]);
            }
        }
        __syncthreads();
    }

    // epilogue: D[m][co] -> g_y2
    const int rbase = m0 + (lane >> 2);
    const int cbase = n0 + 2*(lane & 3);
#pragma unroll
    for (int f = 0; f < 2; f++)
#pragma unroll
        for (int half = 0; half < 2; half++) {
            int m = mt*128 + rbase + f*16 + half*8;
            int nimg = m >> 8, p = m & 255;
            float* op = g_y2 + (size_t)nimg*128*256 + p;
#pragma unroll
            for (int nf = 0; nf < 8; nf++) {
                int co = cbase + nf*8;
                op[(size_t)co*256]     = acc[f][nf][half*2];
                op[(size_t)(co+1)*256] = acc[f][nf][half*2 + 1];
            }
        }

    // fused BN2 stats partials over this block's 128 rows
    float* sred = (float*)dsm;            // [8][64]
    float* qred = (float*)dsm + 512;      // [8][64]
    float cs[8][2], cq[8][2];
#pragma unroll
    for (int nf = 0; nf < 8; nf++)
#pragma unroll
        for (int j = 0; j < 2; j++) {
            float s = acc[0][nf][j] + acc[0][nf][2+j] + acc[1][nf][j] + acc[1][nf][2+j];
            float q = acc[0][nf][j]*acc[0][nf][j] + acc[0][nf][2+j]*acc[0][nf][2+j]
                    + acc[1][nf][j]*acc[1][nf][j] + acc[1][nf][2+j]*acc[1][nf][2+j];
#pragma unroll
            for (int off = 4; off <= 16; off <<= 1) {
                s += __shfl_xor_sync(0xffffffffu, s, off);
                q += __shfl_xor_sync(0xffffffffu, q, off);
            }
            cs[nf][j] = s; cq[nf][j] = q;
        }
    if (lane < 4) {
#pragma unroll
        for (int nf = 0; nf < 8; nf++)
#pragma unroll
            for (int j = 0; j < 2; j++) {
                int col = nf*8 + lane*2 + j;
                sred[wid*64 + col] = cs[nf][j];
                qred[wid*64 + col] = cq[nf][j];
            }
    }
    __syncthreads();
    if (tid < 128) {
        int h = tid >> 6, col = tid & 63;
        float s = 0.0f, q = 0.0f;
#pragma unroll
        for (int mq = 0; mq < 4; mq++) {
            s += sred[(h*4 + mq)*64 + col];
            q += qred[(h*4 + mq)*64 + col];
        }
        g_p2parts[(h*64 + col)*2048 + mt] = s;
        g_p2partq[(h*64 + col)*2048 + mt] = q;
    }
}

// ---------------- BN + LIF + pool, layer 2 ----------------
__global__ void __launch_bounds__(256) lifpool2_kernel()
{
    const int tid = threadIdx.x;
    const int u = blockIdx.x*4 + (tid >> 6);
    const int c = u & 127, b = u >> 7;
    const int pix = tid & 63;
    const int hg = pix >> 3, wg = pix & 7;
    const float sc = g_scale2[c], sh = g_shift2[c];
    float v0 = 0, v1 = 0, v2 = 0, v3 = 0;
#pragma unroll
    for (int t = 0; t < T_; t++) {
        const int n = t*B_ + b;
        const int base = (n*128 + c)*256 + (hg*2)*16 + wg*2;
        float2 r0 = *reinterpret_cast<const float2*>(g_y2 + base);
        float2 r1 = *reinterpret_cast<const float2*>(g_y2 + base + 16);
        float x00 = r0.x*sc + sh, x01 = r0.y*sc + sh;
        float x10 = r1.x*sc + sh, x11 = r1.y*sc + sh;
        float s00, s01, s10, s11;
        LIF_STEP(v0, x00, s00); LIF_STEP(v1, x01, s01);
        LIF_STEP(v2, x10, s10); LIF_STEP(v3, x11, s11);
        g_s2[(n*128 + c)*64 + hg*8 + wg] = (s00 + s01 + s10 + s11)*0.25f;
    }
}

// ---------------- fc1 A repack ----------------
__global__ void __launch_bounds__(256) repack_fcA_kernel()
{
    int gid = blockIdx.x*256 + threadIdx.x;    // 524288
    int c32 = gid & 3, r = (gid >> 2) & 127, kc = (gid >> 9) & 127, mt = gid >> 16;
    int m = mt*128 + r;
    unsigned pk[8];
    __nv_bfloat16 v2[2];
#pragma unroll
    for (int e = 0; e < 16; e++) {
        int k = kc*64 + c32*16 + e;
        v2[e & 1] = __float2bfloat16(g_s2[(size_t)m*8192 + k]);
        if (e & 1) pk[e >> 1] = pack_bf2(v2[0], v2[1]);
    }
    __nv_bfloat16* base = g_afc + ((size_t)mt*128 + kc)*8192;
    int ua = r*8 + ((2*c32) ^ (r & 7));
    int ub = r*8 + ((2*c32 + 1) ^ (r & 7));
    *(uint4*)(base + ua*8) = make_uint4(pk[0], pk[1], pk[2], pk[3]);
    *(uint4*)(base + ub*8) = make_uint4(pk[4], pk[5], pk[6], pk[7]);
}

// ---------------- fc1 weight 3-split ----------------
__global__ void __launch_bounds__(256) prep_fc1_w_kernel(const float* __restrict__ w)
{
    int gid = blockIdx.x*256 + threadIdx.x;    // 131072
    int c32 = gid & 3, r = (gid >> 2) & 127, kc = (gid >> 9) & 127, nt = gid >> 16;
    int co = nt*128 + r;
    unsigned hi[8], mid[8], lo[8];
    __nv_bfloat16 h2[2], m2[2], l2[2];
#pragma unroll
    for (int e = 0; e < 16; e++) {
        int k = kc*64 + c32*16 + e;
        float wv = w[(size_t)co*8192 + k];
        __nv_bfloat16 h = __float2bfloat16(wv);
        float r1 = wv - __bfloat162float(h);
        __nv_bfloat16 m = __float2bfloat16(r1);
        float r2 = r1 - __bfloat162float(m);
        __nv_bfloat16 l = __float2bfloat16(r2);
        h2[e & 1] = h; m2[e & 1] = m; l2[e & 1] = l;
        if (e & 1) {
            hi[e >> 1] = pack_bf2(h2[0], h2[1]);
            mid[e >> 1] = pack_bf2(m2[0], m2[1]);
            lo[e >> 1] = pack_bf2(l2[0], l2[1]);
        }
    }
    int ua = r*8 + ((2*c32) ^ (r & 7));
    int ub = r*8 + ((2*c32 + 1) ^ (r & 7));
    for (int s = 0; s < 3; s++) {
        unsigned* src = (s == 0) ? hi : (s == 1) ? mid : lo;
        __nv_bfloat16* base = g_bfc + (((size_t)nt*128 + kc)*3 + s)*8192;
        *(uint4*)(base + ua*8) = make_uint4(src[0], src[1], src[2], src[3]);
        *(uint4*)(base + ub*8) = make_uint4(src[4], src[5], src[6], src[7]);
    }
}

// ---------------- fc1 GEMM with K-split 8 ----------------
__global__ void __launch_bounds__(256) fc1_gemm_kernel()
{
    extern __shared__ char dsm[];
    const unsigned sbase = smem_u32(dsm);
    const int tid = threadIdx.x, lane = tid & 31, wid = tid >> 5;
    const int mt = blockIdx.x, nt = blockIdx.y, ksl = blockIdx.z;
    const int m0 = (wid & 3) * 32, n0 = (wid >> 2) * 64;
    const int kc0 = ksl*16;

    float acc[2][8][4];
#pragma unroll
    for (int f = 0; f < 2; f++)
#pragma unroll
        for (int nf = 0; nf < 8; nf++)
#pragma unroll
            for (int q = 0; q < 4; q++) acc[f][nf][q] = 0.0f;

    {
        unsigned dst = sbase;
        const char* ag = (const char*)(g_afc + ((size_t)mt*128 + kc0)*8192);
#pragma unroll
        for (int i = 0; i < 4; i++)
            CP16(dst + (unsigned)(tid + i*256)*16, ag + (size_t)(tid + i*256)*16);
        const char* bg = (const char*)(g_bfc + ((size_t)nt*128 + kc0)*3*8192);
#pragma unroll
        for (int i = 0; i < 12; i++)
            CP16(dst + 16384u + (unsigned)(tid + i*256)*16, bg + (size_t)(tid + i*256)*16);
        CP_COMMIT();
    }

#pragma unroll 1
    for (int j = 0; j < 16; j++) {
        const int cur = j & 1;
        if (j < 15) {
            const int kc = kc0 + j + 1;
            unsigned dst = sbase + (unsigned)(cur ^ 1)*65536u;
            const char* ag = (const char*)(g_afc + ((size_t)mt*128 + kc)*8192);
#pragma unroll
            for (int i = 0; i < 4; i++)
                CP16(dst + (unsigned)(tid + i*256)*16, ag + (size_t)(tid + i*256)*16);
            const char* bg = (const char*)(g_bfc + ((size_t)nt*128 + kc)*3*8192);
#pragma unroll
            for (int i = 0; i < 12; i++)
                CP16(dst + 16384u + (unsigned)(tid + i*256)*16, bg + (size_t)(tid + i*256)*16);
            CP_COMMIT();
            CP_WAIT1();
        } else {
            CP_WAIT0();
        }
        __syncthreads();

        const unsigned sA = sbase + (unsigned)cur*65536u;
        const unsigned sB = sA + 16384u;

        unsigned afr[4][2][4];
#pragma unroll
        for (int ks = 0; ks < 4; ks++)
#pragma unroll
            for (int f = 0; f < 2; f++) {
                int row = m0 + f*16 + (lane & 15);
                int c16 = ks*2 + (lane >> 4);
                unsigned ad = sA + (unsigned)((row*8 + (c16 ^ (row & 7)))*16);
                ldsm4(afr[ks][f][0], afr[ks][f][1], afr[ks][f][2], afr[ks][f][3], ad);
            }

#pragma unroll 1
        for (int s = 0; s < 3; s++) {
            const unsigned bb = sB + (unsigned)s*16384u;
#pragma unroll
            for (int ks = 0; ks < 4; ks++) {
                unsigned bfr[8][2];
#pragma unroll
                for (int nb = 0; nb < 4; nb++) {
                    int row = n0 + nb*16 + (lane & 7) + ((lane >> 4) << 3);
                    int c16 = ks*2 + ((lane >> 3) & 1);
                    unsigned ad = bb + (unsigned)((row*8 + (c16 ^ (row & 7)))*16);
                    unsigned r0, r1, r2, r3;
                    ldsm4(r0, r1, r2, r3, ad);
                    bfr[2*nb][0] = r0; bfr[2*nb][1] = r1;
                    bfr[2*nb+1][0] = r2; bfr[2*nb+1][1] = r3;
                }
#pragma unroll
                for (int f = 0; f < 2; f++)
#pragma unroll
                    for (int nf = 0; nf < 8; nf++)
                        mma_bf16(acc[f][nf], afr[ks][f], bfr[nf]);
            }
        }
        __syncthreads();
    }

    const int rbase = m0 + (lane >> 2);
    const int cbase = n0 + 2*(lane & 3);
    float* outp = g_z1p + (size_t)ksl*262144;
#pragma unroll
    for (int f = 0; f < 2; f++)
#pragma unroll
        for (int half = 0; half < 2; half++) {
            int m = mt*128 + rbase + f*16 + half*8;
            float* op = outp + (size_t)m*256 + nt*128;
#pragma unroll
            for (int nf = 0; nf < 8; nf++) {
                int col = cbase + nf*8;
                op[col]     = acc[f][nf][half*2];
                op[col + 1] = acc[f][nf][half*2 + 1];
            }
        }
}

// ---------------- K-split reduce + LIF on fc1 output ----------------
__global__ void __launch_bounds__(256) lif_fc_kernel()
{
    const int gid = blockIdx.x*256 + threadIdx.x;   // 32768
    const int o = gid & 255, b = gid >> 8;
    const int S = 262144;
    float v = 0.0f;
#pragma unroll
    for (int t = 0; t < T_; t++) {
        const int idx = (t*B_ + b)*256 + o;
        float x = g_z1p[idx];
        x += g_z1p[S + idx];   x += g_z1p[2*S + idx]; x += g_z1p[3*S + idx];
        x += g_z1p[4*S + idx]; x += g_z1p[5*S + idx]; x += g_z1p[6*S + idx];
        x += g_z1p[7*S + idx];
        float s;
        LIF_STEP(v, x, s);
        g_s3[idx] = s;
    }
}

// ---------------- fc2 + bias ----------------
__global__ void __launch_bounds__(256) fc2_kernel(const float* __restrict__ w2,
                                                  const float* __restrict__ b2,
                                                  float* __restrict__ out)
{
    const int gid = blockIdx.x*256 + threadIdx.x;
    if (gid >= N_*10) return;
    const int smp = gid / 10, o = gid - smp*10;
    const float4* xs = reinterpret_cast<const float4*>(g_s3 + smp*256);
    const float4* ws = reinterpret_cast<const float4*>(w2 + o*256);
    float acc = 0.0f;
#pragma unroll 8
    for (int i = 0; i < 64; i++) {
        float4 a = xs[i], wv = ws[i];
        acc += a.x*wv.x; acc += a.y*wv.y; acc += a.z*wv.z; acc += a.w*wv.w;
    }
    out[gid] = acc + b2[o];
}

// ---------------- launcher ----------------
extern "C" void kernel_launch(void* const* d_in, const int* in_sizes, int n_in,
                              void* d_out, int out_size)
{
    const float* x    = (const float*)d_in[0];
    const float* c1w  = (const float*)d_in[1];
    const float* bn1g = (const float*)d_in[2];
    const float* bn1b = (const float*)d_in[3];
    const float* c2w  = (const float*)d_in[4];
    const float* bn2g = (const float*)d_in[5];
    const float* bn2b = (const float*)d_in[6];
    const float* fc1w = (const float*)d_in[7];
    const float* fc2w = (const float*)d_in[8];
    const float* fc2b = (const float*)d_in[9];
    float* out = (float*)d_out;

    cudaFuncSetAttribute(conv2_gemm_kernel, cudaFuncAttributeMaxDynamicSharedMemorySize, 131072);
    cudaFuncSetAttribute(fc1_gemm_kernel,   cudaFuncAttributeMaxDynamicSharedMemorySize, 131072);

    conv1_kernel<<<1024, 256>>>(x, c1w);
    finalize1_kernel<<<1, 64>>>(bn1g, bn1b);
    lifpool1_kernel<<<8192, 256>>>();

    prep_conv2_w_kernel<<<18, 256>>>(c2w);
    im2col2_kernel<<<36864, 256>>>();
    conv2_gemm_kernel<<<2048, 256, 131072>>>();
    finalize2_kernel<<<1, 128>>>(bn2g, bn2b);
    lifpool2_kernel<<<4096, 256>>>();

    repack_fcA_kernel<<<2048, 256>>>();
    prep_fc1_w_kernel<<<512, 256>>>(fc1w);
    fc1_gemm_kernel<<<dim3(8, 2, 8), 256, 131072>>>();

    lif_fc_kernel<<<128, 256>>>();
    fc2_kernel<<<40, 256>>>(fc2w, fc2b, out);
}

// round 11
// speedup vs baseline: 1.5952x; 1.5952x over previous
#include <cuda_runtime.h>
#include <cuda_bf16.h>
#include <math.h>
#include <stdint.h>

#define T_ 8
#define B_ 128
#define N_ 1024

// ---------------- static scratch ----------------
__device__ float g_y1[N_*64*32*32];    // conv1 out (268 MB)
__device__ float g_s1[N_*64*16*16];    // pooled spikes L1
__device__ float g_y2[N_*128*16*16];   // conv2 out (134 MB)
__device__ float g_s2[N_*128*8*8];     // pooled spikes L2
__device__ float g_s3[N_*256];         // LIF spikes L3
__device__ float g_z1p[8*N_*256];      // fc1 K-split partials

__device__ __nv_bfloat16 g_a2[(size_t)2048*9*8192];   // conv2 im2col tiles, swizzled
__device__ __nv_bfloat16 g_b2[9*3*8192];              // conv2 weight tiles [kc][split]
__device__ __nv_bfloat16 g_afc[(size_t)8*128*8192];   // fc1 A tiles
__device__ __nv_bfloat16 g_bfc[(size_t)2*128*3*8192]; // fc1 B tiles

__device__ float g_p1parts[64*1024], g_p1partq[64*1024];   // conv1 fused stats partials
__device__ float g_p2parts[128*2048], g_p2partq[128*2048]; // conv2 fused stats partials
__device__ float g_scale1[64], g_shift1[64];
__device__ float g_scale2[128], g_shift2[128];

#define LIF_STEP(v, x, s)                         \
    {                                             \
        v = v + (x - v) * 0.5f;                   \
        s = (v >= 1.0f) ? 1.0f : 0.0f;            \
        v = (v >= 1.0f) ? 0.0f : v;               \
    }

__device__ __forceinline__ unsigned smem_u32(const void* p) {
    return (unsigned)__cvta_generic_to_shared(p);
}
__device__ __forceinline__ unsigned pack_bf2(__nv_bfloat16 a, __nv_bfloat16 b) {
    return (unsigned)__bfloat16_as_ushort(a) | ((unsigned)__bfloat16_as_ushort(b) << 16);
}

#define CP16(dst, src) \
    asm volatile("cp.async.cg.shared.global [%0], [%1], 16;" :: "r"(dst), "l"(src))
#define CP_COMMIT() asm volatile("cp.async.commit_group;" ::: "memory")
#define CP_WAIT1()  asm volatile("cp.async.wait_group 1;" ::: "memory")
#define CP_WAIT0()  asm volatile("cp.async.wait_group 0;" ::: "memory")

__device__ __forceinline__ void ldsm4(unsigned& r0, unsigned& r1, unsigned& r2, unsigned& r3,
                                      unsigned a) {
    asm volatile("ldmatrix.sync.aligned.m8n8.x4.shared.b16 {%0,%1,%2,%3}, [%4];"
                 : "=r"(r0), "=r"(r1), "=r"(r2), "=r"(r3) : "r"(a));
}
__device__ __forceinline__ void mma_bf16(float* c, const unsigned* a, const unsigned* b) {
    asm volatile("mma.sync.aligned.m16n8k16.row.col.f32.bf16.bf16.f32 "
                 "{%0,%1,%2,%3}, {%4,%5,%6,%7}, {%8,%9}, {%0,%1,%2,%3};"
                 : "+f"(c[0]), "+f"(c[1]), "+f"(c[2]), "+f"(c[3])
                 : "r"(a[0]), "r"(a[1]), "r"(a[2]), "r"(a[3]), "r"(b[0]), "r"(b[1]));
}

// ---------------- conv1: 3->64, 32x32, pad 1, fused BN1 stats partials ----------------
__global__ void __launch_bounds__(256) conv1_kernel(const float* __restrict__ x,
                                                    const float* __restrict__ w)
{
    __shared__ float s_in[3*34*34];
    __shared__ float s_w[64*27];
    __shared__ float c1s[8][8], c1q[8][8];
    const int n = blockIdx.x, tid = threadIdx.x;
    const int lane = tid & 31, wid = tid >> 5;

    for (int i = tid; i < 3*34*34; i += 256) s_in[i] = 0.0f;
    __syncthreads();
    for (int i = tid; i < 3*1024; i += 256) {
        int ci = i >> 10, p = i & 1023, h = p >> 5, wc = p & 31;
        s_in[ci*1156 + (h+1)*34 + (wc+1)] = x[n*3072 + i];
    }
    for (int i = tid; i < 1728; i += 256) s_w[i] = w[i];
    __syncthreads();

    int hh[4], ww[4];
#pragma unroll
    for (int j = 0; j < 4; j++) { int p = tid + j*256; hh[j] = p >> 5; ww[j] = p & 31; }

#pragma unroll 1
    for (int cb = 0; cb < 64; cb += 8) {
        float acc[8][4];
#pragma unroll
        for (int u = 0; u < 8; u++)
#pragma unroll
            for (int j = 0; j < 4; j++) acc[u][j] = 0.0f;

#pragma unroll
        for (int ci = 0; ci < 3; ci++)
#pragma unroll
        for (int kh = 0; kh < 3; kh++)
#pragma unroll
        for (int kw = 0; kw < 3; kw++) {
            const int k = ci*9 + kh*3 + kw;
            float wr[8];
#pragma unroll
            for (int u = 0; u < 8; u++) wr[u] = s_w[(cb+u)*27 + k];
#pragma unroll
            for (int j = 0; j < 4; j++) {
                float xv = s_in[ci*1156 + (hh[j]+kh)*34 + (ww[j]+kw)];
#pragma unroll
                for (int u = 0; u < 8; u++) acc[u][j] += wr[u] * xv;
            }
        }
#pragma unroll
        for (int u = 0; u < 8; u++)
#pragma unroll
            for (int j = 0; j < 4; j++)
                g_y1[(n*64 + cb + u)*1024 + tid + j*256] = acc[u][j];

        // fused BN1 stats partials for these 8 channels
#pragma unroll
        for (int u = 0; u < 8; u++) {
            float fs = acc[u][0] + acc[u][1] + acc[u][2] + acc[u][3];
            float fq = acc[u][0]*acc[u][0] + acc[u][1]*acc[u][1]
                     + acc[u][2]*acc[u][2] + acc[u][3]*acc[u][3];
#pragma unroll
            for (int off = 16; off > 0; off >>= 1) {
                fs += __shfl_xor_sync(0xffffffffu, fs, off);
                fq += __shfl_xor_sync(0xffffffffu, fq, off);
            }
            if (lane == 0) { c1s[wid][u] = fs; c1q[wid][u] = fq; }
        }
        __syncthreads();
        if (tid < 8) {
            float s = 0.0f, q = 0.0f;
#pragma unroll
            for (int wv = 0; wv < 8; wv++) { s += c1s[wv][tid]; q += c1q[wv][tid]; }
            g_p1parts[(cb + tid)*1024 + n] = s;
            g_p1partq[(cb + tid)*1024 + n] = q;
        }
        __syncthreads();
    }
}

// ---------------- parallel finalize: one block per channel, fp64 tree ----------------
__global__ void __launch_bounds__(256) finalize1_kernel(const float* __restrict__ g,
                                                        const float* __restrict__ b)
{
    const int c = blockIdx.x, tid = threadIdx.x;
    double s = 0.0, q = 0.0;
#pragma unroll
    for (int i = 0; i < 4; i++) {
        int idx = c*1024 + tid + i*256;
        s += (double)g_p1parts[idx];
        q += (double)g_p1partq[idx];
    }
    __shared__ double ss[256], sq[256];
    ss[tid] = s; sq[tid] = q; __syncthreads();
    for (int st = 128; st > 0; st >>= 1) {
        if (tid < st) { ss[tid] += ss[tid+st]; sq[tid] += sq[tid+st]; }
        __syncthreads();
    }
    if (tid == 0) {
        const double cnt = 1048576.0;
        double m = ss[0] / cnt, var = sq[0] / cnt - m*m;
        double sc = (double)g[c] / sqrt(var + 1e-5);
        g_scale1[c] = (float)sc;
        g_shift1[c] = (float)((double)b[c] - m*sc);
    }
}

__global__ void __launch_bounds__(256) finalize2_kernel(const float* __restrict__ g,
                                                        const float* __restrict__ b)
{
    const int c = blockIdx.x, tid = threadIdx.x;
    double s = 0.0, q = 0.0;
#pragma unroll
    for (int i = 0; i < 8; i++) {
        int idx = c*2048 + tid + i*256;
        s += (double)g_p2parts[idx];
        q += (double)g_p2partq[idx];
    }
    __shared__ double ss[256], sq[256];
    ss[tid] = s; sq[tid] = q; __syncthreads();
    for (int st = 128; st > 0; st >>= 1) {
        if (tid < st) { ss[tid] += ss[tid+st]; sq[tid] += sq[tid+st]; }
        __syncthreads();
    }
    if (tid == 0) {
        const double cnt = 262144.0;
        double m = ss[0] / cnt, var = sq[0] / cnt - m*m;
        double sc = (double)g[c] / sqrt(var + 1e-5);
        g_scale2[c] = (float)sc;
        g_shift2[c] = (float)((double)b[c] - m*sc);
    }
}

// ---------------- BN + LIF + pool, layer 1 ----------------
__global__ void __launch_bounds__(256) lifpool1_kernel()
{
    const int bc = blockIdx.x;
    const int c = bc & 63, b = bc >> 6;
    const int tid = threadIdx.x;
    const int hg = tid >> 4, wg = tid & 15;
    const float sc = g_scale1[c], sh = g_shift1[c];
    float v0 = 0, v1 = 0, v2 = 0, v3 = 0;
#pragma unroll
    for (int t = 0; t < T_; t++) {
        const int n = t*B_ + b;
        const int base = (n*64 + c)*1024 + (hg*2)*32 + wg*2;
        float2 r0 = *reinterpret_cast<const float2*>(g_y1 + base);
        float2 r1 = *reinterpret_cast<const float2*>(g_y1 + base + 32);
        float x00 = r0.x*sc + sh, x01 = r0.y*sc + sh;
        float x10 = r1.x*sc + sh, x11 = r1.y*sc + sh;
        float s00, s01, s10, s11;
        LIF_STEP(v0, x00, s00); LIF_STEP(v1, x01, s01);
        LIF_STEP(v2, x10, s10); LIF_STEP(v3, x11, s11);
        g_s1[(n*64 + c)*256 + hg*16 + wg] = (s00 + s01 + s10 + s11)*0.25f;
    }
}

// ---------------- conv2 weight 3-split into swizzled bf16 tiles ----------------
__global__ void __launch_bounds__(256) prep_conv2_w_kernel(const float* __restrict__ w)
{
    int gid = blockIdx.x*256 + threadIdx.x;     // 9*128*4 = 4608
    if (gid >= 4608) return;
    int c32 = gid & 3, co = (gid >> 2) & 127, kc = gid >> 9;
    unsigned hi[8], mid[8], lo[8];
    __nv_bfloat16 h2[2], m2[2], l2[2];
#pragma unroll
    for (int e = 0; e < 16; e++) {
        int k = kc*64 + c32*16 + e;
        float wv = w[co*576 + k];
        __nv_bfloat16 h = __float2bfloat16(wv);
        float r1 = wv - __bfloat162float(h);
        __nv_bfloat16 m = __float2bfloat16(r1);
        float r2 = r1 - __bfloat162float(m);
        __nv_bfloat16 l = __float2bfloat16(r2);
        h2[e & 1] = h; m2[e & 1] = m; l2[e & 1] = l;
        if (e & 1) {
            hi[e >> 1] = pack_bf2(h2[0], h2[1]);
            mid[e >> 1] = pack_bf2(m2[0], m2[1]);
            lo[e >> 1] = pack_bf2(l2[0], l2[1]);
        }
    }
    int r = co;
    int ua = r*8 + ((2*c32) ^ (r & 7));
    int ub = r*8 + ((2*c32 + 1) ^ (r & 7));
    for (int s = 0; s < 3; s++) {
        unsigned* src = (s == 0) ? hi : (s == 1) ? mid : lo;
        __nv_bfloat16* base = g_b2 + ((size_t)kc*3 + s)*8192;
        *(uint4*)(base + ua*8) = make_uint4(src[0], src[1], src[2], src[3]);
        *(uint4*)(base + ub*8) = make_uint4(src[4], src[5], src[6], src[7]);
    }
}

// ---------------- im2col for conv2 ----------------
__global__ void __launch_bounds__(256) im2col2_kernel()
{
    int gid = blockIdx.x*256 + threadIdx.x;     // 9*4*262144
    int m = gid & 262143;
    int rest = gid >> 18;
    int c32 = rest & 3, kc = rest >> 2;
    int n = m >> 8, p = m & 255, h = p >> 4, w = p & 15;
    int mt = m >> 7, r = m & 127;
    unsigned pk[8];
    __nv_bfloat16 v2[2];
#pragma unroll
    for (int e = 0; e < 16; e++) {
        int k = kc*64 + c32*16 + e;
        int ci = k / 9, t9 = k - ci*9, kh = t9 / 3, kw = t9 - kh*3;
        int ih = h + kh - 1, iw = w + kw - 1;
        float v = 0.0f;
        if ((unsigned)ih < 16u && (unsigned)iw < 16u)
            v = g_s1[((n*64 + ci) << 8) + (ih << 4) + iw];
        v2[e & 1] = __float2bfloat16(v);
        if (e & 1) pk[e >> 1] = pack_bf2(v2[0], v2[1]);
    }
    __nv_bfloat16* base = g_a2 + ((size_t)mt*9 + kc)*8192;
    int ua = r*8 + ((2*c32) ^ (r & 7));
    int ub = r*8 + ((2*c32 + 1) ^ (r & 7));
    *(uint4*)(base + ua*8) = make_uint4(pk[0], pk[1], pk[2], pk[3]);
    *(uint4*)(base + ub*8) = make_uint4(pk[4], pk[5], pk[6], pk[7]);
}

// ---------------- conv2 GEMM (R4 mainloop) + fused BN2 stats epilogue ----------------
__global__ void __launch_bounds__(256) conv2_gemm_kernel()
{
    extern __shared__ char dsm[];
    const unsigned sbase = smem_u32(dsm);
    const int tid = threadIdx.x, lane = tid & 31, wid = tid >> 5;
    const int mt = blockIdx.x;
    const int m0 = (wid & 3) * 32, n0 = (wid >> 2) * 64;

    float acc[2][8][4];
#pragma unroll
    for (int f = 0; f < 2; f++)
#pragma unroll
        for (int nf = 0; nf < 8; nf++)
#pragma unroll
            for (int q = 0; q < 4; q++) acc[f][nf][q] = 0.0f;

    {
        unsigned dst = sbase;
        const char* ag = (const char*)(g_a2 + ((size_t)mt*9 + 0)*8192);
#pragma unroll
        for (int i = 0; i < 4; i++)
            CP16(dst + (unsigned)(tid + i*256)*16, ag + (size_t)(tid + i*256)*16);
        const char* bg = (const char*)(g_b2);
#pragma unroll
        for (int i = 0; i < 12; i++)
            CP16(dst + 16384u + (unsigned)(tid + i*256)*16, bg + (size_t)(tid + i*256)*16);
        CP_COMMIT();
    }

#pragma unroll 1
    for (int kc = 0; kc < 9; kc++) {
        const int cur = kc & 1;
        if (kc < 8) {
            unsigned dst = sbase + (unsigned)(cur ^ 1)*65536u;
            const char* ag = (const char*)(g_a2 + ((size_t)mt*9 + kc + 1)*8192);
#pragma unroll
            for (int i = 0; i < 4; i++)
                CP16(dst + (unsigned)(tid + i*256)*16, ag + (size_t)(tid + i*256)*16);
            const char* bg = (const char*)(g_b2 + (size_t)(kc + 1)*3*8192);
#pragma unroll
            for (int i = 0; i < 12; i++)
                CP16(dst + 16384u + (unsigned)(tid + i*256)*16, bg + (size_t)(tid + i*256)*16);
            CP_COMMIT();
            CP_WAIT1();
        } else {
            CP_WAIT0();
        }
        __syncthreads();

        const unsigned sA = sbase + (unsigned)cur*65536u;
        const unsigned sB = sA + 16384u;

        unsigned afr[4][2][4];
#pragma unroll
        for (int ks = 0; ks < 4; ks++)
#pragma unroll
            for (int f = 0; f < 2; f++) {
                int row = m0 + f*16 + (lane & 15);
                int c16 = ks*2 + (lane >> 4);
                unsigned ad = sA + (unsigned)((row*8 + (c16 ^ (row & 7)))*16);
                ldsm4(afr[ks][f][0], afr[ks][f][1], afr[ks][f][2], afr[ks][f][3], ad);
            }

#pragma unroll 1
        for (int s = 0; s < 3; s++) {
            const unsigned bb = sB + (unsigned)s*16384u;
#pragma unroll
            for (int ks = 0; ks < 4; ks++) {
                unsigned bfr[8][2];
#pragma unroll
                for (int nb = 0; nb < 4; nb++) {
                    int row = n0 + nb*16 + (lane & 7) + ((lane >> 4) << 3);
                    int c16 = ks*2 + ((lane >> 3) & 1);
                    unsigned ad = bb + (unsigned)((row*8 + (c16 ^ (row & 7)))*16);
                    unsigned r0, r1, r2, r3;
                    ldsm4(r0, r1, r2, r3, ad);
                    bfr[2*nb][0] = r0; bfr[2*nb][1] = r1;
                    bfr[2*nb+1][0] = r2; bfr[2*nb+1][1] = r3;
                }
#pragma unroll
                for (int f = 0; f < 2; f++)
#pragma unroll
                    for (int nf = 0; nf < 8; nf++)
                        mma_bf16(acc[f][nf], afr[ks][f], bfr[nf]);
            }
        }
        __syncthreads();
    }

    // epilogue: D[m][co] -> g_y2
    const int rbase = m0 + (lane >> 2);
    const int cbase = n0 + 2*(lane & 3);
#pragma unroll
    for (int f = 0; f < 2; f++)
#pragma unroll
        for (int half = 0; half < 2; half++) {
            int m = mt*128 + rbase + f*16 + half*8;
            int nimg = m >> 8, p = m & 255;
            float* op = g_y2 + (size_t)nimg*128*256 + p;
#pragma unroll
            for (int nf = 0; nf < 8; nf++) {
                int co = cbase + nf*8;
                op[(size_t)co*256]     = acc[f][nf][half*2];
                op[(size_t)(co+1)*256] = acc[f][nf][half*2 + 1];
            }
        }

    // fused BN2 stats partials over this block's 128 rows
    float* sred = (float*)dsm;            // [8][64]
    float* qred = (float*)dsm + 512;      // [8][64]
    float cs[8][2], cq[8][2];
#pragma unroll
    for (int nf = 0; nf < 8; nf++)
#pragma unroll
        for (int j = 0; j < 2; j++) {
            float s = acc[0][nf][j] + acc[0][nf][2+j] + acc[1][nf][j] + acc[1][nf][2+j];
            float q = acc[0][nf][j]*acc[0][nf][j] + acc[0][nf][2+j]*acc[0][nf][2+j]
                    + acc[1][nf][j]*acc[1][nf][j] + acc[1][nf][2+j]*acc[1][nf][2+j];
#pragma unroll
            for (int off = 4; off <= 16; off <<= 1) {
                s += __shfl_xor_sync(0xffffffffu, s, off);
                q += __shfl_xor_sync(0xffffffffu, q, off);
            }
            cs[nf][j] = s; cq[nf][j] = q;
        }
    if (lane < 4) {
#pragma unroll
        for (int nf = 0; nf < 8; nf++)
#pragma unroll
            for (int j = 0; j < 2; j++) {
                int col = nf*8 + lane*2 + j;
                sred[wid*64 + col] = cs[nf][j];
                qred[wid*64 + col] = cq[nf][j];
            }
    }
    __syncthreads();
    if (tid < 128) {
        int h = tid >> 6, col = tid & 63;
        float s = 0.0f, q = 0.0f;
#pragma unroll
        for (int mq = 0; mq < 4; mq++) {
            s += sred[(h*4 + mq)*64 + col];
            q += qred[(h*4 + mq)*64 + col];
        }
        g_p2parts[(h*64 + col)*2048 + mt] = s;
        g_p2partq[(h*64 + col)*2048 + mt] = q;
    }
}

// ---------------- BN + LIF + pool, layer 2 ----------------
__global__ void __launch_bounds__(256) lifpool2_kernel()
{
    const int tid = threadIdx.x;
    const int u = blockIdx.x*4 + (tid >> 6);
    const int c = u & 127, b = u >> 7;
    const int pix = tid & 63;
    const int hg = pix >> 3, wg = pix & 7;
    const float sc = g_scale2[c], sh = g_shift2[c];
    float v0 = 0, v1 = 0, v2 = 0, v3 = 0;
#pragma unroll
    for (int t = 0; t < T_; t++) {
        const int n = t*B_ + b;
        const int base = (n*128 + c)*256 + (hg*2)*16 + wg*2;
        float2 r0 = *reinterpret_cast<const float2*>(g_y2 + base);
        float2 r1 = *reinterpret_cast<const float2*>(g_y2 + base + 16);
        float x00 = r0.x*sc + sh, x01 = r0.y*sc + sh;
        float x10 = r1.x*sc + sh, x11 = r1.y*sc + sh;
        float s00, s01, s10, s11;
        LIF_STEP(v0, x00, s00); LIF_STEP(v1, x01, s01);
        LIF_STEP(v2, x10, s10); LIF_STEP(v3, x11, s11);
        g_s2[(n*128 + c)*64 + hg*8 + wg] = (s00 + s01 + s10 + s11)*0.25f;
    }
}

// ---------------- fc1 A repack ----------------
__global__ void __launch_bounds__(256) repack_fcA_kernel()
{
    int gid = blockIdx.x*256 + threadIdx.x;    // 524288
    int c32 = gid & 3, r = (gid >> 2) & 127, kc = (gid >> 9) & 127, mt = gid >> 16;
    int m = mt*128 + r;
    unsigned pk[8];
    __nv_bfloat16 v2[2];
#pragma unroll
    for (int e = 0; e < 16; e++) {
        int k = kc*64 + c32*16 + e;
        v2[e & 1] = __float2bfloat16(g_s2[(size_t)m*8192 + k]);
        if (e & 1) pk[e >> 1] = pack_bf2(v2[0], v2[1]);
    }
    __nv_bfloat16* base = g_afc + ((size_t)mt*128 + kc)*8192;
    int ua = r*8 + ((2*c32) ^ (r & 7));
    int ub = r*8 + ((2*c32 + 1) ^ (r & 7));
    *(uint4*)(base + ua*8) = make_uint4(pk[0], pk[1], pk[2], pk[3]);
    *(uint4*)(base + ub*8) = make_uint4(pk[4], pk[5], pk[6], pk[7]);
}

// ---------------- fc1 weight 3-split ----------------
__global__ void __launch_bounds__(256) prep_fc1_w_kernel(const float* __restrict__ w)
{
    int gid = blockIdx.x*256 + threadIdx.x;    // 131072
    int c32 = gid & 3, r = (gid >> 2) & 127, kc = (gid >> 9) & 127, nt = gid >> 16;
    int co = nt*128 + r;
    unsigned hi[8], mid[8], lo[8];
    __nv_bfloat16 h2[2], m2[2], l2[2];
#pragma unroll
    for (int e = 0; e < 16; e++) {
        int k = kc*64 + c32*16 + e;
        float wv = w[(size_t)co*8192 + k];
        __nv_bfloat16 h = __float2bfloat16(wv);
        float r1 = wv - __bfloat162float(h);
        __nv_bfloat16 m = __float2bfloat16(r1);
        float r2 = r1 - __bfloat162float(m);
        __nv_bfloat16 l = __float2bfloat16(r2);
        h2[e & 1] = h; m2[e & 1] = m; l2[e & 1] = l;
        if (e & 1) {
            hi[e >> 1] = pack_bf2(h2[0], h2[1]);
            mid[e >> 1] = pack_bf2(m2[0], m2[1]);
            lo[e >> 1] = pack_bf2(l2[0], l2[1]);
        }
    }
    int ua = r*8 + ((2*c32) ^ (r & 7));
    int ub = r*8 + ((2*c32 + 1) ^ (r & 7));
    for (int s = 0; s < 3; s++) {
        unsigned* src = (s == 0) ? hi : (s == 1) ? mid : lo;
        __nv_bfloat16* base = g_bfc + (((size_t)nt*128 + kc)*3 + s)*8192;
        *(uint4*)(base + ua*8) = make_uint4(src[0], src[1], src[2], src[3]);
        *(uint4*)(base + ub*8) = make_uint4(src[4], src[5], src[6], src[7]);
    }
}

// ---------------- fc1 GEMM with K-split 8 ----------------
__global__ void __launch_bounds__(256) fc1_gemm_kernel()
{
    extern __shared__ char dsm[];
    const unsigned sbase = smem_u32(dsm);
    const int tid = threadIdx.x, lane = tid & 31, wid = tid >> 5;
    const int mt = blockIdx.x, nt = blockIdx.y, ksl = blockIdx.z;
    const int m0 = (wid & 3) * 32, n0 = (wid >> 2) * 64;
    const int kc0 = ksl*16;

    float acc[2][8][4];
#pragma unroll
    for (int f = 0; f < 2; f++)
#pragma unroll
        for (int nf = 0; nf < 8; nf++)
#pragma unroll
            for (int q = 0; q < 4; q++) acc[f][nf][q] = 0.0f;

    {
        unsigned dst = sbase;
        const char* ag = (const char*)(g_afc + ((size_t)mt*128 + kc0)*8192);
#pragma unroll
        for (int i = 0; i < 4; i++)
            CP16(dst + (unsigned)(tid + i*256)*16, ag + (size_t)(tid + i*256)*16);
        const char* bg = (const char*)(g_bfc + ((size_t)nt*128 + kc0)*3*8192);
#pragma unroll
        for (int i = 0; i < 12; i++)
            CP16(dst + 16384u + (unsigned)(tid + i*256)*16, bg + (size_t)(tid + i*256)*16);
        CP_COMMIT();
    }

#pragma unroll 1
    for (int j = 0; j < 16; j++) {
        const int cur = j & 1;
        if (j < 15) {
            const int kc = kc0 + j + 1;
            unsigned dst = sbase + (unsigned)(cur ^ 1)*65536u;
            const char* ag = (const char*)(g_afc + ((size_t)mt*128 + kc)*8192);
#pragma unroll
            for (int i = 0; i < 4; i++)
                CP16(dst + (unsigned)(tid + i*256)*16, ag + (size_t)(tid + i*256)*16);
            const char* bg = (const char*)(g_bfc + ((size_t)nt*128 + kc)*3*8192);
#pragma unroll
            for (int i = 0; i < 12; i++)
                CP16(dst + 16384u + (unsigned)(tid + i*256)*16, bg + (size_t)(tid + i*256)*16);
            CP_COMMIT();
            CP_WAIT1();
        } else {
            CP_WAIT0();
        }
        __syncthreads();

        const unsigned sA = sbase + (unsigned)cur*65536u;
        const unsigned sB = sA + 16384u;

        unsigned afr[4][2][4];
#pragma unroll
        for (int ks = 0; ks < 4; ks++)
#pragma unroll
            for (int f = 0; f < 2; f++) {
                int row = m0 + f*16 + (lane & 15);
                int c16 = ks*2 + (lane >> 4);
                unsigned ad = sA + (unsigned)((row*8 + (c16 ^ (row & 7)))*16);
                ldsm4(afr[ks][f][0], afr[ks][f][1], afr[ks][f][2], afr[ks][f][3], ad);
            }

#pragma unroll 1
        for (int s = 0; s < 3; s++) {
            const unsigned bb = sB + (unsigned)s*16384u;
#pragma unroll
            for (int ks = 0; ks < 4; ks++) {
                unsigned bfr[8][2];
#pragma unroll
                for (int nb = 0; nb < 4; nb++) {
                    int row = n0 + nb*16 + (lane & 7) + ((lane >> 4) << 3);
                    int c16 = ks*2 + ((lane >> 3) & 1);
                    unsigned ad = bb + (unsigned)((row*8 + (c16 ^ (row & 7)))*16);
                    unsigned r0, r1, r2, r3;
                    ldsm4(r0, r1, r2, r3, ad);
                    bfr[2*nb][0] = r0; bfr[2*nb][1] = r1;
                    bfr[2*nb+1][0] = r2; bfr[2*nb+1][1] = r3;
                }
#pragma unroll
                for (int f = 0; f < 2; f++)
#pragma unroll
                    for (int nf = 0; nf < 8; nf++)
                        mma_bf16(acc[f][nf], afr[ks][f], bfr[nf]);
            }
        }
        __syncthreads();
    }

    const int rbase = m0 + (lane >> 2);
    const int cbase = n0 + 2*(lane & 3);
    float* outp = g_z1p + (size_t)ksl*262144;
#pragma unroll
    for (int f = 0; f < 2; f++)
#pragma unroll
        for (int half = 0; half < 2; half++) {
            int m = mt*128 + rbase + f*16 + half*8;
            float* op = outp + (size_t)m*256 + nt*128;
#pragma unroll
            for (int nf = 0; nf < 8; nf++) {
                int col = cbase + nf*8;
                op[col]     = acc[f][nf][half*2];
                op[col + 1] = acc[f][nf][half*2 + 1];
            }
        }
}

// ---------------- K-split reduce + LIF on fc1 output ----------------
__global__ void __launch_bounds__(256) lif_fc_kernel()
{
    const int gid = blockIdx.x*256 + threadIdx.x;   // 32768
    const int o = gid & 255, b = gid >> 8;
    const int S = 262144;
    float v = 0.0f;
#pragma unroll
    for (int t = 0; t < T_; t++) {
        const int idx = (t*B_ + b)*256 + o;
        float x = g_z1p[idx];
        x += g_z1p[S + idx];   x += g_z1p[2*S + idx]; x += g_z1p[3*S + idx];
        x += g_z1p[4*S + idx]; x += g_z1p[5*S + idx]; x += g_z1p[6*S + idx];
        x += g_z1p[7*S + idx];
        float s;
        LIF_STEP(v, x, s);
        g_s3[idx] = s;
    }
}

// ---------------- fc2 + bias ----------------
__global__ void __launch_bounds__(256) fc2_kernel(const float* __restrict__ w2,
                                                  const float* __restrict__ b2,
                                                  float* __restrict__ out)
{
    const int gid = blockIdx.x*256 + threadIdx.x;
    if (gid >= N_*10) return;
    const int smp = gid / 10, o = gid - smp*10;
    const float4* xs = reinterpret_cast<const float4*>(g_s3 + smp*256);
    const float4* ws = reinterpret_cast<const float4*>(w2 + o*256);
    float acc = 0.0f;
#pragma unroll 8
    for (int i = 0; i < 64; i++) {
        float4 a = xs[i], wv = ws[i];
        acc += a.x*wv.x; acc += a.y*wv.y; acc += a.z*wv.z; acc += a.w*wv.w;
    }
    out[gid] = acc + b2[o];
}

// ---------------- launcher ----------------
extern "C" void kernel_launch(void* const* d_in, const int* in_sizes, int n_in,
                              void* d_out, int out_size)
{
    const float* x    = (const float*)d_in[0];
    const float* c1w  = (const float*)d_in[1];
    const float* bn1g = (const float*)d_in[2];
    const float* bn1b = (const float*)d_in[3];
    const float* c2w  = (const float*)d_in[4];
    const float* bn2g = (const float*)d_in[5];
    const float* bn2b = (const float*)d_in[6];
    const float* fc1w = (const float*)d_in[7];
    const float* fc2w = (const float*)d_in[8];
    const float* fc2b = (const float*)d_in[9];
    float* out = (float*)d_out;

    cudaFuncSetAttribute(conv2_gemm_kernel, cudaFuncAttributeMaxDynamicSharedMemorySize, 131072);
    cudaFuncSetAttribute(fc1_gemm_kernel,   cudaFuncAttributeMaxDynamicSharedMemorySize, 131072);

    conv1_kernel<<<1024, 256>>>(x, c1w);
    finalize1_kernel<<<64, 256>>>(bn1g, bn1b);
    lifpool1_kernel<<<8192, 256>>>();

    prep_conv2_w_kernel<<<18, 256>>>(c2w);
    im2col2_kernel<<<36864, 256>>>();
    conv2_gemm_kernel<<<2048, 256, 131072>>>();
    finalize2_kernel<<<128, 256>>>(bn2g, bn2b);
    lifpool2_kernel<<<4096, 256>>>();

    repack_fcA_kernel<<<2048, 256>>>();
    prep_fc1_w_kernel<<<512, 256>>>(fc1w);
    fc1_gemm_kernel<<<dim3(8, 2, 8), 256, 131072>>>();

    lif_fc_kernel<<<128, 256>>>();
    fc2_kernel<<<40, 256>>>(fc2w, fc2b, out);
}

// round 14
// speedup vs baseline: 1.9059x; 1.1948x over previous
#include <cuda_runtime.h>
#include <cuda_bf16.h>
#include <math.h>
#include <stdint.h>

#define T_ 8
#define B_ 128
#define N_ 1024

// ---------------- static scratch ----------------
__device__ float g_y1[N_*64*32*32];            // conv1 out (268 MB)
__device__ __nv_bfloat16 g_s1b[N_*64*16*16];   // pooled spikes L1, [n][c][px] bf16
__device__ __nv_bfloat16 g_s1t[N_*16*16*64];   // pooled spikes L1, [n][px][ci] bf16 (33.5 MB)
__device__ float g_y2t[N_*16*16*128];          // conv2 out, [n][p][co] (134 MB)
__device__ float g_s2t[N_*64*128];             // pooled spikes L2, [n][pp][c]
__device__ float g_s3[N_*256];                 // LIF spikes L3
__device__ float g_z1p[8*N_*256];              // fc1 K-split partials

__device__ __nv_bfloat16 g_b2[9*3*8192];              // conv2 weight tiles [tap][split]
__device__ __nv_bfloat16 g_afc[(size_t)8*128*8192];   // fc1 A tiles
__device__ __nv_bfloat16 g_bfc[(size_t)2*128*3*8192]; // fc1 B tiles

__device__ float g_p1parts[64*1024], g_p1partq[64*1024];
__device__ float g_p2parts[128*2048], g_p2partq[128*2048];
__device__ float g_scale1[64], g_shift1[64];
__device__ float g_scale2[128], g_shift2[128];

#define LIF_STEP(v, x, s)                         \
    {                                             \
        v = v + (x - v) * 0.5f;                   \
        s = (v >= 1.0f) ? 1.0f : 0.0f;            \
        v = (v >= 1.0f) ? 0.0f : v;               \
    }

__device__ __forceinline__ unsigned smem_u32(const void* p) {
    return (unsigned)__cvta_generic_to_shared(p);
}
__device__ __forceinline__ unsigned pack_bf2(__nv_bfloat16 a, __nv_bfloat16 b) {
    return (unsigned)__bfloat16_as_ushort(a) | ((unsigned)__bfloat16_as_ushort(b) << 16);
}

#define CP16(dst, src) \
    asm volatile("cp.async.cg.shared.global [%0], [%1], 16;" :: "r"(dst), "l"(src))
#define CP16Z(dst, src, sz) \
    asm volatile("cp.async.cg.shared.global [%0], [%1], 16, %2;" :: "r"(dst), "l"(src), "r"(sz))
#define CP_COMMIT() asm volatile("cp.async.commit_group;" ::: "memory")
#define CP_WAIT1()  asm volatile("cp.async.wait_group 1;" ::: "memory")
#define CP_WAIT0()  asm volatile("cp.async.wait_group 0;" ::: "memory")

__device__ __forceinline__ void ldsm4(unsigned& r0, unsigned& r1, unsigned& r2, unsigned& r3,
                                      unsigned a) {
    asm volatile("ldmatrix.sync.aligned.m8n8.x4.shared.b16 {%0,%1,%2,%3}, [%4];"
                 : "=r"(r0), "=r"(r1), "=r"(r2), "=r"(r3) : "r"(a));
}
__device__ __forceinline__ void mma_bf16(float* c, const unsigned* a, const unsigned* b) {
    asm volatile("mma.sync.aligned.m16n8k16.row.col.f32.bf16.bf16.f32 "
                 "{%0,%1,%2,%3}, {%4,%5,%6,%7}, {%8,%9}, {%0,%1,%2,%3};"
                 : "+f"(c[0]), "+f"(c[1]), "+f"(c[2]), "+f"(c[3])
                 : "r"(a[0]), "r"(a[1]), "r"(a[2]), "r"(a[3]), "r"(b[0]), "r"(b[1]));
}

// ---------------- conv1: 3->64, 32x32, pad 1, fused BN1 stats partials ----------------
__global__ void __launch_bounds__(256) conv1_kernel(const float* __restrict__ x,
                                                    const float* __restrict__ w)
{
    __shared__ float s_in[3*34*34];
    __shared__ float s_w[64*27];
    __shared__ float c1s[8][8], c1q[8][8];
    const int n = blockIdx.x, tid = threadIdx.x;
    const int lane = tid & 31, wid = tid >> 5;

    for (int i = tid; i < 3*34*34; i += 256) s_in[i] = 0.0f;
    __syncthreads();
    for (int i = tid; i < 3*1024; i += 256) {
        int ci = i >> 10, p = i & 1023, h = p >> 5, wc = p & 31;
        s_in[ci*1156 + (h+1)*34 + (wc+1)] = x[n*3072 + i];
    }
    for (int i = tid; i < 1728; i += 256) s_w[i] = w[i];
    __syncthreads();

    int hh[4], ww[4];
#pragma unroll
    for (int j = 0; j < 4; j++) { int p = tid + j*256; hh[j] = p >> 5; ww[j] = p & 31; }

#pragma unroll 1
    for (int cb = 0; cb < 64; cb += 8) {
        float acc[8][4];
#pragma unroll
        for (int u = 0; u < 8; u++)
#pragma unroll
            for (int j = 0; j < 4; j++) acc[u][j] = 0.0f;

#pragma unroll
        for (int ci = 0; ci < 3; ci++)
#pragma unroll
        for (int kh = 0; kh < 3; kh++)
#pragma unroll
        for (int kw = 0; kw < 3; kw++) {
            const int k = ci*9 + kh*3 + kw;
            float wr[8];
#pragma unroll
            for (int u = 0; u < 8; u++) wr[u] = s_w[(cb+u)*27 + k];
#pragma unroll
            for (int j = 0; j < 4; j++) {
                float xv = s_in[ci*1156 + (hh[j]+kh)*34 + (ww[j]+kw)];
#pragma unroll
                for (int u = 0; u < 8; u++) acc[u][j] += wr[u] * xv;
            }
        }
#pragma unroll
        for (int u = 0; u < 8; u++)
#pragma unroll
            for (int j = 0; j < 4; j++)
                g_y1[(n*64 + cb + u)*1024 + tid + j*256] = acc[u][j];

#pragma unroll
        for (int u = 0; u < 8; u++) {
            float fs = acc[u][0] + acc[u][1] + acc[u][2] + acc[u][3];
            float fq = acc[u][0]*acc[u][0] + acc[u][1]*acc[u][1]
                     + acc[u][2]*acc[u][2] + acc[u][3]*acc[u][3];
#pragma unroll
            for (int off = 16; off > 0; off >>= 1) {
                fs += __shfl_xor_sync(0xffffffffu, fs, off);
                fq += __shfl_xor_sync(0xffffffffu, fq, off);
            }
            if (lane == 0) { c1s[wid][u] = fs; c1q[wid][u] = fq; }
        }
        __syncthreads();
        if (tid < 8) {
            float s = 0.0f, q = 0.0f;
#pragma unroll
            for (int wv = 0; wv < 8; wv++) { s += c1s[wv][tid]; q += c1q[wv][tid]; }
            g_p1parts[(cb + tid)*1024 + n] = s;
            g_p1partq[(cb + tid)*1024 + n] = q;
        }
        __syncthreads();
    }
}

// ---------------- parallel finalize ----------------
__global__ void __launch_bounds__(256) finalize1_kernel(const float* __restrict__ g,
                                                        const float* __restrict__ b)
{
    const int c = blockIdx.x, tid = threadIdx.x;
    double s = 0.0, q = 0.0;
#pragma unroll
    for (int i = 0; i < 4; i++) {
        int idx = c*1024 + tid + i*256;
        s += (double)g_p1parts[idx];
        q += (double)g_p1partq[idx];
    }
    __shared__ double ss[256], sq[256];
    ss[tid] = s; sq[tid] = q; __syncthreads();
    for (int st = 128; st > 0; st >>= 1) {
        if (tid < st) { ss[tid] += ss[tid+st]; sq[tid] += sq[tid+st]; }
        __syncthreads();
    }
    if (tid == 0) {
        const double cnt = 1048576.0;
        double m = ss[0] / cnt, var = sq[0] / cnt - m*m;
        double sc = (double)g[c] / sqrt(var + 1e-5);
        g_scale1[c] = (float)sc;
        g_shift1[c] = (float)((double)b[c] - m*sc);
    }
}

__global__ void __launch_bounds__(256) finalize2_kernel(const float* __restrict__ g,
                                                        const float* __restrict__ b)
{
    const int c = blockIdx.x, tid = threadIdx.x;
    double s = 0.0, q = 0.0;
#pragma unroll
    for (int i = 0; i < 8; i++) {
        int idx = c*2048 + tid + i*256;
        s += (double)g_p2parts[idx];
        q += (double)g_p2partq[idx];
    }
    __shared__ double ss[256], sq[256];
    ss[tid] = s; sq[tid] = q; __syncthreads();
    for (int st = 128; st > 0; st >>= 1) {
        if (tid < st) { ss[tid] += ss[tid+st]; sq[tid] += sq[tid+st]; }
        __syncthreads();
    }
    if (tid == 0) {
        const double cnt = 262144.0;
        double m = ss[0] / cnt, var = sq[0] / cnt - m*m;
        double sc = (double)g[c] / sqrt(var + 1e-5);
        g_scale2[c] = (float)sc;
        g_shift2[c] = (float)((double)b[c] - m*sc);
    }
}

// ---------------- BN + LIF + pool, layer 1 (bf16 spikes, [n][c][px]) ----------------
__global__ void __launch_bounds__(256) lifpool1_kernel()
{
    const int bc = blockIdx.x;
    const int c = bc & 63, b = bc >> 6;
    const int tid = threadIdx.x;
    const int hg = tid >> 4, wg = tid & 15;
    const float sc = g_scale1[c], sh = g_shift1[c];
    float v0 = 0, v1 = 0, v2 = 0, v3 = 0;
#pragma unroll
    for (int t = 0; t < T_; t++) {
        const int n = t*B_ + b;
        const int base = (n*64 + c)*1024 + (hg*2)*32 + wg*2;
        float2 r0 = *reinterpret_cast<const float2*>(g_y1 + base);
        float2 r1 = *reinterpret_cast<const float2*>(g_y1 + base + 32);
        float x00 = r0.x*sc + sh, x01 = r0.y*sc + sh;
        float x10 = r1.x*sc + sh, x11 = r1.y*sc + sh;
        float s00, s01, s10, s11;
        LIF_STEP(v0, x00, s00); LIF_STEP(v1, x01, s01);
        LIF_STEP(v2, x10, s10); LIF_STEP(v3, x11, s11);
        g_s1b[(n*64 + c)*256 + hg*16 + wg] =
            __float2bfloat16((s00 + s01 + s10 + s11)*0.25f);
    }
}

// ---------------- transpose spikes: [n][c][px] -> [n][px][c] ----------------
__global__ void __launch_bounds__(256) transpose1_kernel()
{
    __shared__ __nv_bfloat16 tile[64][264];   // [c][px], padded
    const int n = blockIdx.x, tid = threadIdx.x;
    // load: thread (c = tid>>2, pxg = tid&3), 8 x uint4 (8 bf16 each)
    {
        const int c = tid >> 2, pxg = tid & 3;
        const uint4* src = (const uint4*)(g_s1b + (n*64 + c)*256 + pxg*64);
#pragma unroll
        for (int i = 0; i < 8; i++) {
            uint4 v = src[i];
            *(uint4*)&tile[c][pxg*64 + i*8] = v;
        }
    }
    __syncthreads();
    // store: 4 passes; thread (px = pass*64 + (tid>>2), u = tid&3) packs 8 c values
#pragma unroll
    for (int pass = 0; pass < 4; pass++) {
        const int px = pass*64 + (tid >> 2);
        const int u = tid & 3;   // covers c = u*16 .. u*16+15 (2 units of 8)
        unsigned pk[8];
#pragma unroll
        for (int j = 0; j < 8; j++) {
            int c0 = u*16 + j*2;
            pk[j] = pack_bf2(tile[c0][px], tile[c0+1][px]);
        }
        uint4* dst = (uint4*)(g_s1t + ((size_t)n*256 + px)*64 + u*16);
        dst[0] = make_uint4(pk[0], pk[1], pk[2], pk[3]);
        dst[1] = make_uint4(pk[4], pk[5], pk[6], pk[7]);
    }
}

// ---------------- conv2 weight 3-split, K order = [tap][ci] ----------------
__global__ void __launch_bounds__(256) prep_conv2_w_kernel(const float* __restrict__ w)
{
    int gid = blockIdx.x*256 + threadIdx.x;     // 9*128*4 = 4608
    if (gid >= 4608) return;
    int c32 = gid & 3, co = (gid >> 2) & 127, kc = gid >> 9;   // kc = tap
    unsigned hi[8], mid[8], lo[8];
    __nv_bfloat16 h2[2], m2[2], l2[2];
#pragma unroll
    for (int e = 0; e < 16; e++) {
        int ci = c32*16 + e;
        float wv = w[co*576 + ci*9 + kc];
        __nv_bfloat16 h = __float2bfloat16(wv);
        float r1 = wv - __bfloat162float(h);
        __nv_bfloat16 m = __float2bfloat16(r1);
        float r2 = r1 - __bfloat162float(m);
        __nv_bfloat16 l = __float2bfloat16(r2);
        h2[e & 1] = h; m2[e & 1] = m; l2[e & 1] = l;
        if (e & 1) {
            hi[e >> 1] = pack_bf2(h2[0], h2[1]);
            mid[e >> 1] = pack_bf2(m2[0], m2[1]);
            lo[e >> 1] = pack_bf2(l2[0], l2[1]);
        }
    }
    int r = co;
    int ua = r*8 + ((2*c32) ^ (r & 7));
    int ub = r*8 + ((2*c32 + 1) ^ (r & 7));
    for (int s = 0; s < 3; s++) {
        unsigned* src = (s == 0) ? hi : (s == 1) ? mid : lo;
        __nv_bfloat16* base = g_b2 + ((size_t)kc*3 + s)*8192;
        *(uint4*)(base + ua*8) = make_uint4(src[0], src[1], src[2], src[3]);
        *(uint4*)(base + ub*8) = make_uint4(src[4], src[5], src[6], src[7]);
    }
}

// ---------------- conv2: GEMM with direct A gather (cp.async + zfill) ----------------
// K chunk kc = tap (kh,kw) over 64 ci. A row (pixel) = contiguous 128B of g_s1t.
__global__ void __launch_bounds__(256) conv2_gemm_kernel()
{
    extern __shared__ char dsm[];
    const unsigned sbase = smem_u32(dsm);
    const int tid = threadIdx.x, lane = tid & 31, wid = tid >> 5;
    const int mt = blockIdx.x;
    const int m0 = (wid & 3) * 32, n0 = (wid >> 2) * 64;

    // A-gather coordinates for this thread (2 threads per row, 4 units each)
    const int gr = tid >> 1;
    const int u0 = (tid & 1) * 4;
    const int gm = mt*128 + gr;
    const int gimg = gm >> 8, gp = gm & 255;
    const int gph = gp >> 4, gpw = gp & 15;

    float acc[2][8][4];
#pragma unroll
    for (int f = 0; f < 2; f++)
#pragma unroll
        for (int nf = 0; nf < 8; nf++)
#pragma unroll
            for (int q = 0; q < 4; q++) acc[f][nf][q] = 0.0f;

    // stage loader: A (16KB, gathered+swizzled) + B (48KB linear)
    auto load_stage = [&](int kc, unsigned stage) {
        const int kh = kc / 3, kw = kc - kh*3;
        const int ih = gph + kh - 1, iw = gpw + kw - 1;
        const bool ok = ((unsigned)ih < 16u) && ((unsigned)iw < 16u);
        const char* srow = ok
            ? (const char*)(g_s1t + ((size_t)gimg*256 + ih*16 + iw)*64)
            : (const char*)g_s1t;
        const unsigned sz = ok ? 16u : 0u;
        const unsigned drow = stage + (unsigned)(gr*128);
#pragma unroll
        for (int uu = 0; uu < 4; uu++) {
            int u = u0 + uu;
            CP16Z(drow + (unsigned)((u ^ (gr & 7))*16), srow + u*16, sz);
        }
        const char* bg = (const char*)(g_b2 + (size_t)kc*3*8192);
#pragma unroll
        for (int i = 0; i < 12; i++)
            CP16(stage + 16384u + (unsigned)(tid + i*256)*16, bg + (size_t)(tid + i*256)*16);
    };

    load_stage(0, sbase);
    CP_COMMIT();

#pragma unroll 1
    for (int kc = 0; kc < 9; kc++) {
        const int cur = kc & 1;
        if (kc < 8) {
            load_stage(kc + 1, sbase + (unsigned)(cur ^ 1)*65536u);
            CP_COMMIT();
            CP_WAIT1();
        } else {
            CP_WAIT0();
        }
        __syncthreads();

        const unsigned sA = sbase + (unsigned)cur*65536u;
        const unsigned sB = sA + 16384u;

        unsigned afr[4][2][4];
#pragma unroll
        for (int ks = 0; ks < 4; ks++)
#pragma unroll
            for (int f = 0; f < 2; f++) {
                int row = m0 + f*16 + (lane & 15);
                int c16 = ks*2 + (lane >> 4);
                unsigned ad = sA + (unsigned)((row*8 + (c16 ^ (row & 7)))*16);
                ldsm4(afr[ks][f][0], afr[ks][f][1], afr[ks][f][2], afr[ks][f][3], ad);
            }

#pragma unroll 1
        for (int s = 0; s < 3; s++) {
            const unsigned bb = sB + (unsigned)s*16384u;
#pragma unroll
            for (int ks = 0; ks < 4; ks++) {
                unsigned bfr[8][2];
#pragma unroll
                for (int nb = 0; nb < 4; nb++) {
                    int row = n0 + nb*16 + (lane & 7) + ((lane >> 4) << 3);
                    int c16 = ks*2 + ((lane >> 3) & 1);
                    unsigned ad = bb + (unsigned)((row*8 + (c16 ^ (row & 7)))*16);
                    unsigned r0, r1, r2, r3;
                    ldsm4(r0, r1, r2, r3, ad);
                    bfr[2*nb][0] = r0; bfr[2*nb][1] = r1;
                    bfr[2*nb+1][0] = r2; bfr[2*nb+1][1] = r3;
                }
#pragma unroll
                for (int f = 0; f < 2; f++)
#pragma unroll
                    for (int nf = 0; nf < 8; nf++)
                        mma_bf16(acc[f][nf], afr[ks][f], bfr[nf]);
            }
        }
        __syncthreads();
    }

    // epilogue: D -> g_y2t [n][p][co], sector-aligned float2 stores
    const int rbase = m0 + (lane >> 2);
    const int cbase = n0 + 2*(lane & 3);
#pragma unroll
    for (int f = 0; f < 2; f++)
#pragma unroll
        for (int half = 0; half < 2; half++) {
            int m = mt*128 + rbase + f*16 + half*8;
            int nimg = m >> 8, p = m & 255;
            float* op = g_y2t + ((size_t)nimg*256 + p)*128;
#pragma unroll
            for (int nf = 0; nf < 8; nf++) {
                int co = cbase + nf*8;
                *(float2*)(op + co) = make_float2(acc[f][nf][half*2], acc[f][nf][half*2+1]);
            }
        }

    // fused BN2 stats partials
    float* sred = (float*)dsm;            // [8][64]
    float* qred = (float*)dsm + 512;      // [8][64]
    float cs[8][2], cq[8][2];
#pragma unroll
    for (int nf = 0; nf < 8; nf++)
#pragma unroll
        for (int j = 0; j < 2; j++) {
            float s = acc[0][nf][j] + acc[0][nf][2+j] + acc[1][nf][j] + acc[1][nf][2+j];
            float q = acc[0][nf][j]*acc[0][nf][j] + acc[0][nf][2+j]*acc[0][nf][2+j]
                    + acc[1][nf][j]*acc[1][nf][j] + acc[1][nf][2+j]*acc[1][nf][2+j];
#pragma unroll
            for (int off = 4; off <= 16; off <<= 1) {
                s += __shfl_xor_sync(0xffffffffu, s, off);
                q += __shfl_xor_sync(0xffffffffu, q, off);
            }
            cs[nf][j] = s; cq[nf][j] = q;
        }
    if (lane < 4) {
#pragma unroll
        for (int nf = 0; nf < 8; nf++)
#pragma unroll
            for (int j = 0; j < 2; j++) {
                int col = nf*8 + lane*2 + j;
                sred[wid*64 + col] = cs[nf][j];
                qred[wid*64 + col] = cq[nf][j];
            }
    }
    __syncthreads();
    if (tid < 128) {
        int h = tid >> 6, col = tid & 63;
        float s = 0.0f, q = 0.0f;
#pragma unroll
        for (int mq = 0; mq < 4; mq++) {
            s += sred[(h*4 + mq)*64 + col];
            q += qred[(h*4 + mq)*64 + col];
        }
        g_p2parts[(h*64 + col)*2048 + mt] = s;
        g_p2partq[(h*64 + col)*2048 + mt] = q;
    }
}

// ---------------- BN + LIF + pool, layer 2 ([n][p][co] -> [n][pp][c]) ----------------
__global__ void __launch_bounds__(256) lifpool2_kernel()
{
    const int u = blockIdx.x;            // 4096 = 128 b * 32 ppg
    const int b = u >> 5, ppg = u & 31;
    const int tid = threadIdx.x;
    const int c = tid & 127;
    const int pp = ppg*2 + (tid >> 7);
    const int hg = pp >> 3, wg = pp & 7;
    const int p00 = (hg*2)*16 + wg*2;
    const float sc = g_scale2[c], sh = g_shift2[c];
    float v0 = 0, v1 = 0, v2 = 0, v3 = 0;
#pragma unroll
    for (int t = 0; t < T_; t++) {
        const int n = t*B_ + b;
        const float* base = g_y2t + (size_t)n*256*128;
        float x00 = base[(p00)*128 + c]*sc + sh;
        float x01 = base[(p00+1)*128 + c]*sc + sh;
        float x10 = base[(p00+16)*128 + c]*sc + sh;
        float x11 = base[(p00+17)*128 + c]*sc + sh;
        float s00, s01, s10, s11;
        LIF_STEP(v0, x00, s00); LIF_STEP(v1, x01, s01);
        LIF_STEP(v2, x10, s10); LIF_STEP(v3, x11, s11);
        g_s2t[((size_t)n*64 + pp)*128 + c] = (s00 + s01 + s10 + s11)*0.25f;
    }
}

// ---------------- fc1 A repack (K order = pp*128 + c) ----------------
__global__ void __launch_bounds__(256) repack_fcA_kernel()
{
    int gid = blockIdx.x*256 + threadIdx.x;    // 524288
    int c32 = gid & 3, r = (gid >> 2) & 127, kc = (gid >> 9) & 127, mt = gid >> 16;
    int m = mt*128 + r;
    unsigned pk[8];
    __nv_bfloat16 v2[2];
#pragma unroll
    for (int e = 0; e < 16; e++) {
        int k = kc*64 + c32*16 + e;
        v2[e & 1] = __float2bfloat16(g_s2t[(size_t)m*8192 + k]);
        if (e & 1) pk[e >> 1] = pack_bf2(v2[0], v2[1]);
    }
    __nv_bfloat16* base = g_afc + ((size_t)mt*128 + kc)*8192;
    int ua = r*8 + ((2*c32) ^ (r & 7));
    int ub = r*8 + ((2*c32 + 1) ^ (r & 7));
    *(uint4*)(base + ua*8) = make_uint4(pk[0], pk[1], pk[2], pk[3]);
    *(uint4*)(base + ub*8) = make_uint4(pk[4], pk[5], pk[6], pk[7]);
}

// ---------------- fc1 weight 3-split (remapped K: tile k -> orig c*64+pp) ----------------
__global__ void __launch_bounds__(256) prep_fc1_w_kernel(const float* __restrict__ w)
{
    int gid = blockIdx.x*256 + threadIdx.x;    // 131072
    int c32 = gid & 3, r = (gid >> 2) & 127, kc = (gid >> 9) & 127, nt = gid >> 16;
    int co = nt*128 + r;
    unsigned hi[8], mid[8], lo[8];
    __nv_bfloat16 h2[2], m2[2], l2[2];
#pragma unroll
    for (int e = 0; e < 16; e++) {
        int k = kc*64 + c32*16 + e;      // tile K index = pp*128 + c
        int pp = k >> 7, cc = k & 127;
        float wv = w[(size_t)co*8192 + cc*64 + pp];
        __nv_bfloat16 h = __float2bfloat16(wv);
        float r1 = wv - __bfloat162float(h);
        __nv_bfloat16 m = __float2bfloat16(r1);
        float r2 = r1 - __bfloat162float(m);
        __nv_bfloat16 l = __float2bfloat16(r2);
        h2[e & 1] = h; m2[e & 1] = m; l2[e & 1] = l;
        if (e & 1) {
            hi[e >> 1] = pack_bf2(h2[0], h2[1]);
            mid[e >> 1] = pack_bf2(m2[0], m2[1]);
            lo[e >> 1] = pack_bf2(l2[0], l2[1]);
        }
    }
    int ua = r*8 + ((2*c32) ^ (r & 7));
    int ub = r*8 + ((2*c32 + 1) ^ (r & 7));
    for (int s = 0; s < 3; s++) {
        unsigned* src = (s == 0) ? hi : (s == 1) ? mid : lo;
        __nv_bfloat16* base = g_bfc + (((size_t)nt*128 + kc)*3 + s)*8192;
        *(uint4*)(base + ua*8) = make_uint4(src[0], src[1], src[2], src[3]);
        *(uint4*)(base + ub*8) = make_uint4(src[4], src[5], src[6], src[7]);
    }
}

// ---------------- fc1 GEMM with K-split 8 ----------------
__global__ void __launch_bounds__(256) fc1_gemm_kernel()
{
    extern __shared__ char dsm[];
    const unsigned sbase = smem_u32(dsm);
    const int tid = threadIdx.x, lane = tid & 31, wid = tid >> 5;
    const int mt = blockIdx.x, nt = blockIdx.y, ksl = blockIdx.z;
    const int m0 = (wid & 3) * 32, n0 = (wid >> 2) * 64;
    const int kc0 = ksl*16;

    float acc[2][8][4];
#pragma unroll
    for (int f = 0; f < 2; f++)
#pragma unroll
        for (int nf = 0; nf < 8; nf++)
#pragma unroll
            for (int q = 0; q < 4; q++) acc[f][nf][q] = 0.0f;

    {
        unsigned dst = sbase;
        const char* ag = (const char*)(g_afc + ((size_t)mt*128 + kc0)*8192);
#pragma unroll
        for (int i = 0; i < 4; i++)
            CP16(dst + (unsigned)(tid + i*256)*16, ag + (size_t)(tid + i*256)*16);
        const char* bg = (const char*)(g_bfc + ((size_t)nt*128 + kc0)*3*8192);
#pragma unroll
        for (int i = 0; i < 12; i++)
            CP16(dst + 16384u + (unsigned)(tid + i*256)*16, bg + (size_t)(tid + i*256)*16);
        CP_COMMIT();
    }

#pragma unroll 1
    for (int j = 0; j < 16; j++) {
        const int cur = j & 1;
        if (j < 15) {
            const int kc = kc0 + j + 1;
            unsigned dst = sbase + (unsigned)(cur ^ 1)*65536u;
            const char* ag = (const char*)(g_afc + ((size_t)mt*128 + kc)*8192);
#pragma unroll
            for (int i = 0; i < 4; i++)
                CP16(dst + (unsigned)(tid + i*256)*16, ag + (size_t)(tid + i*256)*16);
            const char* bg = (const char*)(g_bfc + ((size_t)nt*128 + kc)*3*8192);
#pragma unroll
            for (int i = 0; i < 12; i++)
                CP16(dst + 16384u + (unsigned)(tid + i*256)*16, bg + (size_t)(tid + i*256)*16);
            CP_COMMIT();
            CP_WAIT1();
        } else {
            CP_WAIT0();
        }
        __syncthreads();

        const unsigned sA = sbase + (unsigned)cur*65536u;
        const unsigned sB = sA + 16384u;

        unsigned afr[4][2][4];
#pragma unroll
        for (int ks = 0; ks < 4; ks++)
#pragma unroll
            for (int f = 0; f < 2; f++) {
                int row = m0 + f*16 + (lane & 15);
                int c16 = ks*2 + (lane >> 4);
                unsigned ad = sA + (unsigned)((row*8 + (c16 ^ (row & 7)))*16);
                ldsm4(afr[ks][f][0], afr[ks][f][1], afr[ks][f][2], afr[ks][f][3], ad);
            }

#pragma unroll 1
        for (int s = 0; s < 3; s++) {
            const unsigned bb = sB + (unsigned)s*16384u;
#pragma unroll
            for (int ks = 0; ks < 4; ks++) {
                unsigned bfr[8][2];
#pragma unroll
                for (int nb = 0; nb < 4; nb++) {
                    int row = n0 + nb*16 + (lane & 7) + ((lane >> 4) << 3);
                    int c16 = ks*2 + ((lane >> 3) & 1);
                    unsigned ad = bb + (unsigned)((row*8 + (c16 ^ (row & 7)))*16);
                    unsigned r0, r1, r2, r3;
                    ldsm4(r0, r1, r2, r3, ad);
                    bfr[2*nb][0] = r0; bfr[2*nb][1] = r1;
                    bfr[2*nb+1][0] = r2; bfr[2*nb+1][1] = r3;
                }
#pragma unroll
                for (int f = 0; f < 2; f++)
#pragma unroll
                    for (int nf = 0; nf < 8; nf++)
                        mma_bf16(acc[f][nf], afr[ks][f], bfr[nf]);
            }
        }
        __syncthreads();
    }

    const int rbase = m0 + (lane >> 2);
    const int cbase = n0 + 2*(lane & 3);
    float* outp = g_z1p + (size_t)ksl*262144;
#pragma unroll
    for (int f = 0; f < 2; f++)
#pragma unroll
        for (int half = 0; half < 2; half++) {
            int m = mt*128 + rbase + f*16 + half*8;
            float* op = outp + (size_t)m*256 + nt*128;
#pragma unroll
            for (int nf = 0; nf < 8; nf++) {
                int col = cbase + nf*8;
                op[col]     = acc[f][nf][half*2];
                op[col + 1] = acc[f][nf][half*2 + 1];
            }
        }
}

// ---------------- K-split reduce + LIF on fc1 output ----------------
__global__ void __launch_bounds__(256) lif_fc_kernel()
{
    const int gid = blockIdx.x*256 + threadIdx.x;   // 32768
    const int o = gid & 255, b = gid >> 8;
    const int S = 262144;
    float v = 0.0f;
#pragma unroll
    for (int t = 0; t < T_; t++) {
        const int idx = (t*B_ + b)*256 + o;
        float x = g_z1p[idx];
        x += g_z1p[S + idx];   x += g_z1p[2*S + idx]; x += g_z1p[3*S + idx];
        x += g_z1p[4*S + idx]; x += g_z1p[5*S + idx]; x += g_z1p[6*S + idx];
        x += g_z1p[7*S + idx];
        float s;
        LIF_STEP(v, x, s);
        g_s3[idx] = s;
    }
}

// ---------------- fc2 + bias ----------------
__global__ void __launch_bounds__(256) fc2_kernel(const float* __restrict__ w2,
                                                  const float* __restrict__ b2,
                                                  float* __restrict__ out)
{
    const int gid = blockIdx.x*256 + threadIdx.x;
    if (gid >= N_*10) return;
    const int smp = gid / 10, o = gid - smp*10;
    const float4* xs = reinterpret_cast<const float4*>(g_s3 + smp*256);
    const float4* ws = reinterpret_cast<const float4*>(w2 + o*256);
    float acc = 0.0f;
#pragma unroll 8
    for (int i = 0; i < 64; i++) {
        float4 a = xs[i], wv = ws[i];
        acc += a.x*wv.x; acc += a.y*wv.y; acc += a.z*wv.z; acc += a.w*wv.w;
    }
    out[gid] = acc + b2[o];
}

// ---------------- launcher ----------------
extern "C" void kernel_launch(void* const* d_in, const int* in_sizes, int n_in,
                              void* d_out, int out_size)
{
    const float* x    = (const float*)d_in[0];
    const float* c1w  = (const float*)d_in[1];
    const float* bn1g = (const float*)d_in[2];
    const float* bn1b = (const float*)d_in[3];
    const float* c2w  = (const float*)d_in[4];
    const float* bn2g = (const float*)d_in[5];
    const float* bn2b = (const float*)d_in[6];
    const float* fc1w = (const float*)d_in[7];
    const float* fc2w = (const float*)d_in[8];
    const float* fc2b = (const float*)d_in[9];
    float* out = (float*)d_out;

    cudaFuncSetAttribute(conv2_gemm_kernel, cudaFuncAttributeMaxDynamicSharedMemorySize, 131072);
    cudaFuncSetAttribute(fc1_gemm_kernel,   cudaFuncAttributeMaxDynamicSharedMemorySize, 131072);

    conv1_kernel<<<1024, 256>>>(x, c1w);
    finalize1_kernel<<<64, 256>>>(bn1g, bn1b);
    lifpool1_kernel<<<8192, 256>>>();
    transpose1_kernel<<<1024, 256>>>();

    prep_conv2_w_kernel<<<18, 256>>>(c2w);
    conv2_gemm_kernel<<<2048, 256, 131072>>>();
    finalize2_kernel<<<128, 256>>>(bn2g, bn2b);
    lifpool2_kernel<<<4096, 256>>>();

    repack_fcA_kernel<<<2048, 256>>>();
    prep_fc1_w_kernel<<<512, 256>>>(fc1w);
    fc1_gemm_kernel<<<dim3(8, 2, 8), 256, 131072>>>();

    lif_fc_kernel<<<128, 256>>>();
    fc2_kernel<<<40, 256>>>(fc2w, fc2b, out);
}

// round 15
// speedup vs baseline: 2.3877x; 1.2528x over previous
#include <cuda_runtime.h>
#include <cuda_fp16.h>
#include <math.h>
#include <stdint.h>

#define T_ 8
#define B_ 128
#define N_ 1024

// ---------------- static scratch ----------------
__device__ float g_y1[N_*64*32*32];        // conv1 out (268 MB)
__device__ __half g_s1b[N_*64*16*16];      // pooled spikes L1, [n][c][px] fp16
__device__ __half g_s1t[N_*16*16*64];      // pooled spikes L1, [n][px][ci] fp16 (33.5 MB)
__device__ float g_y2t[N_*16*16*128];      // conv2 out, [n][p][co] (134 MB)
__device__ float g_s3[N_*256];             // LIF spikes L3
__device__ float g_z1p[8*N_*256];          // fc1 K-split partials

__device__ __half g_b2[9*2*8192];                // conv2 weight tiles [tap][split]
__device__ __half g_afc[(size_t)8*128*8192];     // fc1 A tiles (written by fused lifpool2)
__device__ __half g_bfc[(size_t)2*128*2*8192];   // fc1 B tiles [nt][kc][split]

__device__ float g_p1parts[64*1024], g_p1partq[64*1024];
__device__ float g_p2parts[128*2048], g_p2partq[128*2048];
__device__ float g_scale1[64], g_shift1[64];
__device__ float g_scale2[128], g_shift2[128];

#define LIF_STEP(v, x, s)                         \
    {                                             \
        v = v + (x - v) * 0.5f;                   \
        s = (v >= 1.0f) ? 1.0f : 0.0f;            \
        v = (v >= 1.0f) ? 0.0f : v;               \
    }

__device__ __forceinline__ unsigned smem_u32(const void* p) {
    return (unsigned)__cvta_generic_to_shared(p);
}
__device__ __forceinline__ unsigned pack_h2(__half a, __half b) {
    return (unsigned)__half_as_ushort(a) | ((unsigned)__half_as_ushort(b) << 16);
}

#define CP16(dst, src) \
    asm volatile("cp.async.cg.shared.global [%0], [%1], 16;" :: "r"(dst), "l"(src))
#define CP16Z(dst, src, sz) \
    asm volatile("cp.async.cg.shared.global [%0], [%1], 16, %2;" :: "r"(dst), "l"(src), "r"(sz))
#define CP_COMMIT() asm volatile("cp.async.commit_group;" ::: "memory")
#define CP_WAIT1()  asm volatile("cp.async.wait_group 1;" ::: "memory")
#define CP_WAIT0()  asm volatile("cp.async.wait_group 0;" ::: "memory")

__device__ __forceinline__ void ldsm4(unsigned& r0, unsigned& r1, unsigned& r2, unsigned& r3,
                                      unsigned a) {
    asm volatile("ldmatrix.sync.aligned.m8n8.x4.shared.b16 {%0,%1,%2,%3}, [%4];"
                 : "=r"(r0), "=r"(r1), "=r"(r2), "=r"(r3) : "r"(a));
}
__device__ __forceinline__ void mma_f16(float* c, const unsigned* a, const unsigned* b) {
    asm volatile("mma.sync.aligned.m16n8k16.row.col.f32.f16.f16.f32 "
                 "{%0,%1,%2,%3}, {%4,%5,%6,%7}, {%8,%9}, {%0,%1,%2,%3};"
                 : "+f"(c[0]), "+f"(c[1]), "+f"(c[2]), "+f"(c[3])
                 : "r"(a[0]), "r"(a[1]), "r"(a[2]), "r"(a[3]), "r"(b[0]), "r"(b[1]));
}

// ---------------- conv1: 3->64, 32x32, pad 1, fused BN1 stats partials ----------------
__global__ void __launch_bounds__(256) conv1_kernel(const float* __restrict__ x,
                                                    const float* __restrict__ w)
{
    __shared__ float s_in[3*34*34];
    __shared__ float s_w[64*27];
    __shared__ float c1s[8][8], c1q[8][8];
    const int n = blockIdx.x, tid = threadIdx.x;
    const int lane = tid & 31, wid = tid >> 5;

    for (int i = tid; i < 3*34*34; i += 256) s_in[i] = 0.0f;
    __syncthreads();
    for (int i = tid; i < 3*1024; i += 256) {
        int ci = i >> 10, p = i & 1023, h = p >> 5, wc = p & 31;
        s_in[ci*1156 + (h+1)*34 + (wc+1)] = x[n*3072 + i];
    }
    for (int i = tid; i < 1728; i += 256) s_w[i] = w[i];
    __syncthreads();

    int hh[4], ww[4];
#pragma unroll
    for (int j = 0; j < 4; j++) { int p = tid + j*256; hh[j] = p >> 5; ww[j] = p & 31; }

#pragma unroll 1
    for (int cb = 0; cb < 64; cb += 8) {
        float acc[8][4];
#pragma unroll
        for (int u = 0; u < 8; u++)
#pragma unroll
            for (int j = 0; j < 4; j++) acc[u][j] = 0.0f;

#pragma unroll
        for (int ci = 0; ci < 3; ci++)
#pragma unroll
        for (int kh = 0; kh < 3; kh++)
#pragma unroll
        for (int kw = 0; kw < 3; kw++) {
            const int k = ci*9 + kh*3 + kw;
            float wr[8];
#pragma unroll
            for (int u = 0; u < 8; u++) wr[u] = s_w[(cb+u)*27 + k];
#pragma unroll
            for (int j = 0; j < 4; j++) {
                float xv = s_in[ci*1156 + (hh[j]+kh)*34 + (ww[j]+kw)];
#pragma unroll
                for (int u = 0; u < 8; u++) acc[u][j] += wr[u] * xv;
            }
        }
#pragma unroll
        for (int u = 0; u < 8; u++)
#pragma unroll
            for (int j = 0; j < 4; j++)
                g_y1[(n*64 + cb + u)*1024 + tid + j*256] = acc[u][j];

#pragma unroll
        for (int u = 0; u < 8; u++) {
            float fs = acc[u][0] + acc[u][1] + acc[u][2] + acc[u][3];
            float fq = acc[u][0]*acc[u][0] + acc[u][1]*acc[u][1]
                     + acc[u][2]*acc[u][2] + acc[u][3]*acc[u][3];
#pragma unroll
            for (int off = 16; off > 0; off >>= 1) {
                fs += __shfl_xor_sync(0xffffffffu, fs, off);
                fq += __shfl_xor_sync(0xffffffffu, fq, off);
            }
            if (lane == 0) { c1s[wid][u] = fs; c1q[wid][u] = fq; }
        }
        __syncthreads();
        if (tid < 8) {
            float s = 0.0f, q = 0.0f;
#pragma unroll
            for (int wv = 0; wv < 8; wv++) { s += c1s[wv][tid]; q += c1q[wv][tid]; }
            g_p1parts[(cb + tid)*1024 + n] = s;
            g_p1partq[(cb + tid)*1024 + n] = q;
        }
        __syncthreads();
    }
}

// ---------------- parallel finalize ----------------
__global__ void __launch_bounds__(256) finalize1_kernel(const float* __restrict__ g,
                                                        const float* __restrict__ b)
{
    const int c = blockIdx.x, tid = threadIdx.x;
    double s = 0.0, q = 0.0;
#pragma unroll
    for (int i = 0; i < 4; i++) {
        int idx = c*1024 + tid + i*256;
        s += (double)g_p1parts[idx];
        q += (double)g_p1partq[idx];
    }
    __shared__ double ss[256], sq[256];
    ss[tid] = s; sq[tid] = q; __syncthreads();
    for (int st = 128; st > 0; st >>= 1) {
        if (tid < st) { ss[tid] += ss[tid+st]; sq[tid] += sq[tid+st]; }
        __syncthreads();
    }
    if (tid == 0) {
        const double cnt = 1048576.0;
        double m = ss[0] / cnt, var = sq[0] / cnt - m*m;
        double sc = (double)g[c] / sqrt(var + 1e-5);
        g_scale1[c] = (float)sc;
        g_shift1[c] = (float)((double)b[c] - m*sc);
    }
}

__global__ void __launch_bounds__(256) finalize2_kernel(const float* __restrict__ g,
                                                        const float* __restrict__ b)
{
    const int c = blockIdx.x, tid = threadIdx.x;
    double s = 0.0, q = 0.0;
#pragma unroll
    for (int i = 0; i < 8; i++) {
        int idx = c*2048 + tid + i*256;
        s += (double)g_p2parts[idx];
        q += (double)g_p2partq[idx];
    }
    __shared__ double ss[256], sq[256];
    ss[tid] = s; sq[tid] = q; __syncthreads();
    for (int st = 128; st > 0; st >>= 1) {
        if (tid < st) { ss[tid] += ss[tid+st]; sq[tid] += sq[tid+st]; }
        __syncthreads();
    }
    if (tid == 0) {
        const double cnt = 262144.0;
        double m = ss[0] / cnt, var = sq[0] / cnt - m*m;
        double sc = (double)g[c] / sqrt(var + 1e-5);
        g_scale2[c] = (float)sc;
        g_shift2[c] = (float)((double)b[c] - m*sc);
    }
}

// ---------------- BN + LIF + pool, layer 1 (fp16 spikes, [n][c][px]) ----------------
__global__ void __launch_bounds__(256) lifpool1_kernel()
{
    const int bc = blockIdx.x;
    const int c = bc & 63, b = bc >> 6;
    const int tid = threadIdx.x;
    const int hg = tid >> 4, wg = tid & 15;
    const float sc = g_scale1[c], sh = g_shift1[c];
    float v0 = 0, v1 = 0, v2 = 0, v3 = 0;
#pragma unroll
    for (int t = 0; t < T_; t++) {
        const int n = t*B_ + b;
        const int base = (n*64 + c)*1024 + (hg*2)*32 + wg*2;
        float2 r0 = *reinterpret_cast<const float2*>(g_y1 + base);
        float2 r1 = *reinterpret_cast<const float2*>(g_y1 + base + 32);
        float x00 = r0.x*sc + sh, x01 = r0.y*sc + sh;
        float x10 = r1.x*sc + sh, x11 = r1.y*sc + sh;
        float s00, s01, s10, s11;
        LIF_STEP(v0, x00, s00); LIF_STEP(v1, x01, s01);
        LIF_STEP(v2, x10, s10); LIF_STEP(v3, x11, s11);
        g_s1b[(n*64 + c)*256 + hg*16 + wg] =
            __float2half((s00 + s01 + s10 + s11)*0.25f);
    }
}

// ---------------- transpose spikes: [n][c][px] -> [n][px][c] ----------------
__global__ void __launch_bounds__(256) transpose1_kernel()
{
    __shared__ __half tile[64][264];
    const int n = blockIdx.x, tid = threadIdx.x;
    {
        const int c = tid >> 2, pxg = tid & 3;
        const uint4* src = (const uint4*)(g_s1b + (n*64 + c)*256 + pxg*64);
#pragma unroll
        for (int i = 0; i < 8; i++) {
            uint4 v = src[i];
            *(uint4*)&tile[c][pxg*64 + i*8] = v;
        }
    }
    __syncthreads();
#pragma unroll
    for (int pass = 0; pass < 4; pass++) {
        const int px = pass*64 + (tid >> 2);
        const int u = tid & 3;
        unsigned pk[8];
#pragma unroll
        for (int j = 0; j < 8; j++) {
            int c0 = u*16 + j*2;
            pk[j] = pack_h2(tile[c0][px], tile[c0+1][px]);
        }
        uint4* dst = (uint4*)(g_s1t + ((size_t)n*256 + px)*64 + u*16);
        dst[0] = make_uint4(pk[0], pk[1], pk[2], pk[3]);
        dst[1] = make_uint4(pk[4], pk[5], pk[6], pk[7]);
    }
}

// ---------------- conv2 weight 2-split (fp16 hi/lo), K order = [tap][ci] ----------------
__global__ void __launch_bounds__(256) prep_conv2_w_kernel(const float* __restrict__ w)
{
    int gid = blockIdx.x*256 + threadIdx.x;     // 9*128*4 = 4608
    if (gid >= 4608) return;
    int c32 = gid & 3, co = (gid >> 2) & 127, kc = gid >> 9;   // kc = tap
    unsigned hi[8], lo[8];
    __half h2[2], l2[2];
#pragma unroll
    for (int e = 0; e < 16; e++) {
        int ci = c32*16 + e;
        float wv = w[co*576 + ci*9 + kc];
        __half h = __float2half(wv);
        float r1 = wv - __half2float(h);
        __half l = __float2half(r1);
        h2[e & 1] = h; l2[e & 1] = l;
        if (e & 1) {
            hi[e >> 1] = pack_h2(h2[0], h2[1]);
            lo[e >> 1] = pack_h2(l2[0], l2[1]);
        }
    }
    int r = co;
    int ua = r*8 + ((2*c32) ^ (r & 7));
    int ub = r*8 + ((2*c32 + 1) ^ (r & 7));
    for (int s = 0; s < 2; s++) {
        unsigned* src = (s == 0) ? hi : lo;
        __half* base = g_b2 + ((size_t)kc*2 + s)*8192;
        *(uint4*)(base + ua*8) = make_uint4(src[0], src[1], src[2], src[3]);
        *(uint4*)(base + ub*8) = make_uint4(src[4], src[5], src[6], src[7]);
    }
}

// ---------------- conv2: GEMM with direct A gather + fused BN2 stats ----------------
__global__ void __launch_bounds__(256) conv2_gemm_kernel()
{
    extern __shared__ char dsm[];
    const unsigned sbase = smem_u32(dsm);
    const int tid = threadIdx.x, lane = tid & 31, wid = tid >> 5;
    const int mt = blockIdx.x;
    const int m0 = (wid & 3) * 32, n0 = (wid >> 2) * 64;

    const int gr = tid >> 1;
    const int u0 = (tid & 1) * 4;
    const int gm = mt*128 + gr;
    const int gimg = gm >> 8, gp = gm & 255;
    const int gph = gp >> 4, gpw = gp & 15;

    float acc[2][8][4];
#pragma unroll
    for (int f = 0; f < 2; f++)
#pragma unroll
        for (int nf = 0; nf < 8; nf++)
#pragma unroll
            for (int q = 0; q < 4; q++) acc[f][nf][q] = 0.0f;

    // stage: A 16KB gathered + B 32KB (2 splits)
    auto load_stage = [&](int kc, unsigned stage) {
        const int kh = kc / 3, kw = kc - kh*3;
        const int ih = gph + kh - 1, iw = gpw + kw - 1;
        const bool ok = ((unsigned)ih < 16u) && ((unsigned)iw < 16u);
        const char* srow = ok
            ? (const char*)(g_s1t + ((size_t)gimg*256 + ih*16 + iw)*64)
            : (const char*)g_s1t;
        const unsigned sz = ok ? 16u : 0u;
        const unsigned drow = stage + (unsigned)(gr*128);
#pragma unroll
        for (int uu = 0; uu < 4; uu++) {
            int u = u0 + uu;
            CP16Z(drow + (unsigned)((u ^ (gr & 7))*16), srow + u*16, sz);
        }
        const char* bg = (const char*)(g_b2 + (size_t)kc*2*8192);
#pragma unroll
        for (int i = 0; i < 8; i++)
            CP16(stage + 16384u + (unsigned)(tid + i*256)*16, bg + (size_t)(tid + i*256)*16);
    };

    load_stage(0, sbase);
    CP_COMMIT();

#pragma unroll 1
    for (int kc = 0; kc < 9; kc++) {
        const int cur = kc & 1;
        if (kc < 8) {
            load_stage(kc + 1, sbase + (unsigned)(cur ^ 1)*49152u);
            CP_COMMIT();
            CP_WAIT1();
        } else {
            CP_WAIT0();
        }
        __syncthreads();

        const unsigned sA = sbase + (unsigned)cur*49152u;
        const unsigned sB = sA + 16384u;

        unsigned afr[4][2][4];
#pragma unroll
        for (int ks = 0; ks < 4; ks++)
#pragma unroll
            for (int f = 0; f < 2; f++) {
                int row = m0 + f*16 + (lane & 15);
                int c16 = ks*2 + (lane >> 4);
                unsigned ad = sA + (unsigned)((row*8 + (c16 ^ (row & 7)))*16);
                ldsm4(afr[ks][f][0], afr[ks][f][1], afr[ks][f][2], afr[ks][f][3], ad);
            }

#pragma unroll 1
        for (int s = 0; s < 2; s++) {
            const unsigned bb = sB + (unsigned)s*16384u;
#pragma unroll
            for (int ks = 0; ks < 4; ks++) {
                unsigned bfr[8][2];
#pragma unroll
                for (int nb = 0; nb < 4; nb++) {
                    int row = n0 + nb*16 + (lane & 7) + ((lane >> 4) << 3);
                    int c16 = ks*2 + ((lane >> 3) & 1);
                    unsigned ad = bb + (unsigned)((row*8 + (c16 ^ (row & 7)))*16);
                    unsigned r0, r1, r2, r3;
                    ldsm4(r0, r1, r2, r3, ad);
                    bfr[2*nb][0] = r0; bfr[2*nb][1] = r1;
                    bfr[2*nb+1][0] = r2; bfr[2*nb+1][1] = r3;
                }
#pragma unroll
                for (int f = 0; f < 2; f++)
#pragma unroll
                    for (int nf = 0; nf < 8; nf++)
                        mma_f16(acc[f][nf], afr[ks][f], bfr[nf]);
            }
        }
        __syncthreads();
    }

    // epilogue: D -> g_y2t [n][p][co]
    const int rbase = m0 + (lane >> 2);
    const int cbase = n0 + 2*(lane & 3);
#pragma unroll
    for (int f = 0; f < 2; f++)
#pragma unroll
        for (int half = 0; half < 2; half++) {
            int m = mt*128 + rbase + f*16 + half*8;
            int nimg = m >> 8, p = m & 255;
            float* op = g_y2t + ((size_t)nimg*256 + p)*128;
#pragma unroll
            for (int nf = 0; nf < 8; nf++) {
                int co = cbase + nf*8;
                *(float2*)(op + co) = make_float2(acc[f][nf][half*2], acc[f][nf][half*2+1]);
            }
        }

    // fused BN2 stats partials
    float* sred = (float*)dsm;
    float* qred = (float*)dsm + 512;
    float cs[8][2], cq[8][2];
#pragma unroll
    for (int nf = 0; nf < 8; nf++)
#pragma unroll
        for (int j = 0; j < 2; j++) {
            float s = acc[0][nf][j] + acc[0][nf][2+j] + acc[1][nf][j] + acc[1][nf][2+j];
            float q = acc[0][nf][j]*acc[0][nf][j] + acc[0][nf][2+j]*acc[0][nf][2+j]
                    + acc[1][nf][j]*acc[1][nf][j] + acc[1][nf][2+j]*acc[1][nf][2+j];
#pragma unroll
            for (int off = 4; off <= 16; off <<= 1) {
                s += __shfl_xor_sync(0xffffffffu, s, off);
                q += __shfl_xor_sync(0xffffffffu, q, off);
            }
            cs[nf][j] = s; cq[nf][j] = q;
        }
    __syncthreads();
    if (lane < 4) {
#pragma unroll
        for (int nf = 0; nf < 8; nf++)
#pragma unroll
            for (int j = 0; j < 2; j++) {
                int col = nf*8 + lane*2 + j;
                sred[wid*64 + col] = cs[nf][j];
                qred[wid*64 + col] = cq[nf][j];
            }
    }
    __syncthreads();
    if (tid < 128) {
        int h = tid >> 6, col = tid & 63;
        float s = 0.0f, q = 0.0f;
#pragma unroll
        for (int mq = 0; mq < 4; mq++) {
            s += sred[(h*4 + mq)*64 + col];
            q += qred[(h*4 + mq)*64 + col];
        }
        g_p2parts[(h*64 + col)*2048 + mt] = s;
        g_p2partq[(h*64 + col)*2048 + mt] = q;
    }
}

// ---------------- BN + LIF + pool L2, fused fc1-A repack (fp16 swizzled tiles) ----------------
// thread = (b, pp, 8-channel group); writes one uint4 per t directly into g_afc.
__global__ void __launch_bounds__(256) lifpool2_kernel()
{
    const int bb = blockIdx.x;             // 512 = 128 b * 4 quarters
    const int b = bb >> 2, q4 = bb & 3;
    const int tid = threadIdx.x;
    const int ppl = tid >> 4, cg = tid & 15;
    const int pp = q4*16 + ppl;
    const int c0 = cg*8;
    const int hg = pp >> 3, wg = pp & 7;
    const int p00 = (hg*2)*16 + wg*2;

    float sc[8], sh[8];
#pragma unroll
    for (int j = 0; j < 8; j++) { sc[j] = g_scale2[c0+j]; sh[j] = g_shift2[c0+j]; }

    float v[4][8];
#pragma unroll
    for (int pos = 0; pos < 4; pos++)
#pragma unroll
        for (int j = 0; j < 8; j++) v[pos][j] = 0.0f;

    const int kc = pp*2 + (cg >> 3);
    const int u = cg & 7;
    const int roff = b*64 + ((u ^ (b & 7))*8);

#pragma unroll
    for (int t = 0; t < T_; t++) {
        const int n = t*B_ + b;
        const float* base = g_y2t + (size_t)n*32768;
        const int poff[4] = {p00, p00+1, p00+16, p00+17};
        __half hv[8];
        float pooled[8];
#pragma unroll
        for (int j = 0; j < 8; j++) pooled[j] = 0.0f;
#pragma unroll
        for (int pos = 0; pos < 4; pos++) {
            float4 a0 = *(const float4*)(base + poff[pos]*128 + c0);
            float4 a1 = *(const float4*)(base + poff[pos]*128 + c0 + 4);
            float xv[8] = {a0.x, a0.y, a0.z, a0.w, a1.x, a1.y, a1.z, a1.w};
#pragma unroll
            for (int j = 0; j < 8; j++) {
                float xx = xv[j]*sc[j] + sh[j];
                float s;
                LIF_STEP(v[pos][j], xx, s);
                pooled[j] += s;
            }
        }
#pragma unroll
        for (int j = 0; j < 8; j++) hv[j] = __float2half(pooled[j]*0.25f);

        __half* dst = g_afc + ((size_t)(t*128 + kc))*8192 + roff;
        *(uint4*)dst = make_uint4(pack_h2(hv[0], hv[1]), pack_h2(hv[2], hv[3]),
                                  pack_h2(hv[4], hv[5]), pack_h2(hv[6], hv[7]));
    }
}

// ---------------- fc1 weight 2-split (remapped K: tile k -> orig c*64+pp) ----------------
__global__ void __launch_bounds__(256) prep_fc1_w_kernel(const float* __restrict__ w)
{
    int gid = blockIdx.x*256 + threadIdx.x;    // 131072
    int c32 = gid & 3, r = (gid >> 2) & 127, kc = (gid >> 9) & 127, nt = gid >> 16;
    int co = nt*128 + r;
    unsigned hi[8], lo[8];
    __half h2[2], l2[2];
#pragma unroll
    for (int e = 0; e < 16; e++) {
        int k = kc*64 + c32*16 + e;      // tile K index = pp*128 + c
        int pp = k >> 7, cc = k & 127;
        float wv = w[(size_t)co*8192 + cc*64 + pp];
        __half h = __float2half(wv);
        float r1 = wv - __half2float(h);
        __half l = __float2half(r1);
        h2[e & 1] = h; l2[e & 1] = l;
        if (e & 1) {
            hi[e >> 1] = pack_h2(h2[0], h2[1]);
            lo[e >> 1] = pack_h2(l2[0], l2[1]);
        }
    }
    int ua = r*8 + ((2*c32) ^ (r & 7));
    int ub = r*8 + ((2*c32 + 1) ^ (r & 7));
    for (int s = 0; s < 2; s++) {
        unsigned* src = (s == 0) ? hi : lo;
        __half* base = g_bfc + (((size_t)nt*128 + kc)*2 + s)*8192;
        *(uint4*)(base + ua*8) = make_uint4(src[0], src[1], src[2], src[3]);
        *(uint4*)(base + ub*8) = make_uint4(src[4], src[5], src[6], src[7]);
    }
}

// ---------------- fc1 GEMM with K-split 8 (fp16 2-split) ----------------
__global__ void __launch_bounds__(256) fc1_gemm_kernel()
{
    extern __shared__ char dsm[];
    const unsigned sbase = smem_u32(dsm);
    const int tid = threadIdx.x, lane = tid & 31, wid = tid >> 5;
    const int mt = blockIdx.x, nt = blockIdx.y, ksl = blockIdx.z;
    const int m0 = (wid & 3) * 32, n0 = (wid >> 2) * 64;
    const int kc0 = ksl*16;

    float acc[2][8][4];
#pragma unroll
    for (int f = 0; f < 2; f++)
#pragma unroll
        for (int nf = 0; nf < 8; nf++)
#pragma unroll
            for (int q = 0; q < 4; q++) acc[f][nf][q] = 0.0f;

    auto load_stage = [&](int kc, unsigned stage) {
        const char* ag = (const char*)(g_afc + ((size_t)mt*128 + kc)*8192);
#pragma unroll
        for (int i = 0; i < 4; i++)
            CP16(stage + (unsigned)(tid + i*256)*16, ag + (size_t)(tid + i*256)*16);
        const char* bg = (const char*)(g_bfc + ((size_t)nt*128 + kc)*2*8192);
#pragma unroll
        for (int i = 0; i < 8; i++)
            CP16(stage + 16384u + (unsigned)(tid + i*256)*16, bg + (size_t)(tid + i*256)*16);
    };

    load_stage(kc0, sbase);
    CP_COMMIT();

#pragma unroll 1
    for (int j = 0; j < 16; j++) {
        const int cur = j & 1;
        if (j < 15) {
            load_stage(kc0 + j + 1, sbase + (unsigned)(cur ^ 1)*49152u);
            CP_COMMIT();
            CP_WAIT1();
        } else {
            CP_WAIT0();
        }
        __syncthreads();

        const unsigned sA = sbase + (unsigned)cur*49152u;
        const unsigned sB = sA + 16384u;

        unsigned afr[4][2][4];
#pragma unroll
        for (int ks = 0; ks < 4; ks++)
#pragma unroll
            for (int f = 0; f < 2; f++) {
                int row = m0 + f*16 + (lane & 15);
                int c16 = ks*2 + (lane >> 4);
                unsigned ad = sA + (unsigned)((row*8 + (c16 ^ (row & 7)))*16);
                ldsm4(afr[ks][f][0], afr[ks][f][1], afr[ks][f][2], afr[ks][f][3], ad);
            }

#pragma unroll 1
        for (int s = 0; s < 2; s++) {
            const unsigned bb = sB + (unsigned)s*16384u;
#pragma unroll
            for (int ks = 0; ks < 4; ks++) {
                unsigned bfr[8][2];
#pragma unroll
                for (int nb = 0; nb < 4; nb++) {
                    int row = n0 + nb*16 + (lane & 7) + ((lane >> 4) << 3);
                    int c16 = ks*2 + ((lane >> 3) & 1);
                    unsigned ad = bb + (unsigned)((row*8 + (c16 ^ (row & 7)))*16);
                    unsigned r0, r1, r2, r3;
                    ldsm4(r0, r1, r2, r3, ad);
                    bfr[2*nb][0] = r0; bfr[2*nb][1] = r1;
                    bfr[2*nb+1][0] = r2; bfr[2*nb+1][1] = r3;
                }
#pragma unroll
                for (int f = 0; f < 2; f++)
#pragma unroll
                    for (int nf = 0; nf < 8; nf++)
                        mma_f16(acc[f][nf], afr[ks][f], bfr[nf]);
            }
        }
        __syncthreads();
    }

    const int rbase = m0 + (lane >> 2);
    const int cbase = n0 + 2*(lane & 3);
    float* outp = g_z1p + (size_t)ksl*262144;
#pragma unroll
    for (int f = 0; f < 2; f++)
#pragma unroll
        for (int half = 0; half < 2; half++) {
            int m = mt*128 + rbase + f*16 + half*8;
            float* op = outp + (size_t)m*256 + nt*128;
#pragma unroll
            for (int nf = 0; nf < 8; nf++) {
                int col = cbase + nf*8;
                op[col]     = acc[f][nf][half*2];
                op[col + 1] = acc[f][nf][half*2 + 1];
            }
        }
}

// ---------------- K-split reduce + LIF on fc1 output ----------------
__global__ void __launch_bounds__(256) lif_fc_kernel()
{
    const int gid = blockIdx.x*256 + threadIdx.x;   // 32768
    const int o = gid & 255, b = gid >> 8;
    const int S = 262144;
    float v = 0.0f;
#pragma unroll
    for (int t = 0; t < T_; t++) {
        const int idx = (t*B_ + b)*256 + o;
        float x = g_z1p[idx];
        x += g_z1p[S + idx];   x += g_z1p[2*S + idx]; x += g_z1p[3*S + idx];
        x += g_z1p[4*S + idx]; x += g_z1p[5*S + idx]; x += g_z1p[6*S + idx];
        x += g_z1p[7*S + idx];
        float s;
        LIF_STEP(v, x, s);
        g_s3[idx] = s;
    }
}

// ---------------- fc2 + bias ----------------
__global__ void __launch_bounds__(256) fc2_kernel(const float* __restrict__ w2,
                                                  const float* __restrict__ b2,
                                                  float* __restrict__ out)
{
    const int gid = blockIdx.x*256 + threadIdx.x;
    if (gid >= N_*10) return;
    const int smp = gid / 10, o = gid - smp*10;
    const float4* xs = reinterpret_cast<const float4*>(g_s3 + smp*256);
    const float4* ws = reinterpret_cast<const float4*>(w2 + o*256);
    float acc = 0.0f;
#pragma unroll 8
    for (int i = 0; i < 64; i++) {
        float4 a = xs[i], wv = ws[i];
        acc += a.x*wv.x; acc += a.y*wv.y; acc += a.z*wv.z; acc += a.w*wv.w;
    }
    out[gid] = acc + b2[o];
}

// ---------------- launcher ----------------
extern "C" void kernel_launch(void* const* d_in, const int* in_sizes, int n_in,
                              void* d_out, int out_size)
{
    const float* x    = (const float*)d_in[0];
    const float* c1w  = (const float*)d_in[1];
    const float* bn1g = (const float*)d_in[2];
    const float* bn1b = (const float*)d_in[3];
    const float* c2w  = (const float*)d_in[4];
    const float* bn2g = (const float*)d_in[5];
    const float* bn2b = (const float*)d_in[6];
    const float* fc1w = (const float*)d_in[7];
    const float* fc2w = (const float*)d_in[8];
    const float* fc2b = (const float*)d_in[9];
    float* out = (float*)d_out;

    cudaFuncSetAttribute(conv2_gemm_kernel, cudaFuncAttributeMaxDynamicSharedMemorySize, 98304);
    cudaFuncSetAttribute(fc1_gemm_kernel,   cudaFuncAttributeMaxDynamicSharedMemorySize, 98304);

    conv1_kernel<<<1024, 256>>>(x, c1w);
    finalize1_kernel<<<64, 256>>>(bn1g, bn1b);
    lifpool1_kernel<<<8192, 256>>>();
    transpose1_kernel<<<1024, 256>>>();

    prep_conv2_w_kernel<<<18, 256>>>(c2w);
    conv2_gemm_kernel<<<2048, 256, 98304>>>();
    finalize2_kernel<<<128, 256>>>(bn2g, bn2b);
    lifpool2_kernel<<<512, 256>>>();

    prep_fc1_w_kernel<<<512, 256>>>(fc1w);
    fc1_gemm_kernel<<<dim3(8, 2, 8), 256, 98304>>>();

    lif_fc_kernel<<<128, 256>>>();
    fc2_kernel<<<40, 256>>>(fc2w, fc2b, out);
}